// round 3
// baseline (speedup 1.0000x reference)
#include <cuda_runtime.h>
#include <math.h>

// ---------------- global scratch (no allocations allowed) ----------------
__device__ float q_g[4 * 1024 * 8];
__device__ float k_g[4 * 1024 * 8];
__device__ float v_g[4 * 1024 * 8];
__device__ float attn_g[1024 * 32];

typedef unsigned long long u64;

__device__ __forceinline__ float tanh_f(float x) {
    float y; asm("tanh.approx.f32 %0, %1;" : "=f"(y) : "f"(x)); return y;
}
__device__ __forceinline__ float sigf(float x) {
    return fmaf(0.5f, tanh_f(0.5f * x), 0.5f);
}
__device__ __forceinline__ u64 pack2(float a, float b) {
    u64 r; asm("mov.b64 %0, {%1,%2};" : "=l"(r) : "f"(a), "f"(b)); return r;
}
__device__ __forceinline__ void unpack2(u64 v, float& a, float& b) {
    asm("mov.b64 {%0,%1}, %2;" : "=f"(a), "=f"(b) : "l"(v));
}
__device__ __forceinline__ u64 fma2(u64 a, u64 b, u64 c) {
    u64 d; asm("fma.rn.f32x2 %0, %1, %2, %3;" : "=l"(d) : "l"(a), "l"(b), "l"(c)); return d;
}

// =====================================================================
// Kernel 1: pipelined LSTM1 (group A: threads 0-255) + LSTM2 (group B:
//           threads 256-511) with embedding folded into LSTM1 weights.
//           128 CTAs x 512 threads, 8 batch rows per CTA.
// =====================================================================
__global__ void __launch_bounds__(512, 1) lstm_kernel(
    const float* __restrict__ x,
    const float* __restrict__ emb_w, const float* __restrict__ emb_b,
    const float* __restrict__ w1, const float* __restrict__ u1,
    const float* __restrict__ b1i, const float* __restrict__ b1h,
    const float* __restrict__ w2, const float* __restrict__ u2,
    const float* __restrict__ b2i, const float* __restrict__ b2h,
    const float* __restrict__ attn_w, const float* __restrict__ attn_b)
{
    extern __shared__ __align__(16) float sm[];
    u64* wih2p = (u64*)sm;                 // [64*128] u64 (w,w) pairs
    u64* whh2p = wih2p + 64 * 128;         // [32*128] u64
    float* fb   = (float*)(whh2p + 32 * 128);
    float* pt1s   = fb;                    // [16][256]
    float* bias2s = pt1s + 4096;           // 128
    float* pe     = bias2s + 128;          // [16][32]
    float* embw_s = pe + 512;              // 32
    float* embb_s = embw_s + 32;           // 32
    float* xs     = embb_s + 32;           // [16][8]
    float* h1s    = xs + 128;              // 2 x [64][8]
    float* h2s    = h1s + 1024;            // [32][8]
    float* g1s    = h2s + 256;             // [8][256]
    float* g2s    = g1s + 2048;            // [8][128]

    const int tid = threadIdx.x;
    const int b0 = blockIdx.x * 8;

    // ---- prologue: fill shared structures (all 512 threads) ----
    for (int i = tid; i < 64 * 128; i += 512) {
        int k = i >> 7, g = i & 127;
        float w = w2[g * 64 + k];
        wih2p[i] = pack2(w, w);
    }
    for (int i = tid; i < 32 * 128; i += 512) {
        int k = i >> 7, g = i & 127;
        float w = u2[g * 32 + k];
        whh2p[i] = pack2(w, w);
    }
    if (tid < 512) {
        int t = tid >> 5, e = tid & 31;
        if (tid < 512) {
            int half = e >> 1;
            float div = __expf(-(float)(2 * half) * (9.210340371976184f / 32.0f));
            float arg = (float)t * div;
            pe[tid] = (e & 1) ? cosf(arg) : sinf(arg);
        }
    }
    if (tid < 32) { embw_s[tid] = emb_w[tid]; embb_s[tid] = emb_b[tid]; }
    if (tid < 128) bias2s[tid] = b2i[tid] + b2h[tid];
    if (tid < 128) { int t = tid >> 3, b = tid & 7; xs[tid] = x[(b0 + b) * 16 + t]; }
    for (int i = tid; i < 1024; i += 512) h1s[i] = 0.f;
    if (tid < 256) h2s[tid] = 0.f;
    __syncthreads();

    // ---- per-group register setup ----
    float u1row[64];
    u64 we12 = 0, bv2 = 0;
    float c1r0 = 0.f, c1r1 = 0.f, c2r = 0.f;
    int gB = 0, bg4 = 0;

    if (tid < 256) {
        // group A: LSTM1 gate row `tid`
        const float4* u1p = (const float4*)(u1 + tid * 64);
        #pragma unroll
        for (int q = 0; q < 16; q++) {
            float4 v = u1p[q];
            u1row[q * 4 + 0] = v.x; u1row[q * 4 + 1] = v.y;
            u1row[q * 4 + 2] = v.z; u1row[q * 4 + 3] = v.w;
        }
        float w1r[32];
        const float4* w1p = (const float4*)(w1 + tid * 32);
        #pragma unroll
        for (int q = 0; q < 8; q++) {
            float4 v = w1p[q];
            w1r[q * 4 + 0] = v.x; w1r[q * 4 + 1] = v.y;
            w1r[q * 4 + 2] = v.z; w1r[q * 4 + 3] = v.w;
        }
        float we1 = 0.f, wb = b1i[tid] + b1h[tid];
        #pragma unroll
        for (int e = 0; e < 32; e++) {
            we1 = fmaf(w1r[e], embw_s[e], we1);
            wb  = fmaf(w1r[e], embb_s[e], wb);
        }
        we12 = pack2(we1, we1);
        #pragma unroll
        for (int t = 0; t < 16; t++) {
            float s = wb;
            #pragma unroll
            for (int e = 0; e < 32; e++) s = fmaf(w1r[e], pe[t * 32 + e], s);
            pt1s[t * 256 + tid] = s;
        }
    } else {
        int tid2 = tid - 256;
        gB = tid2 & 127;
        bg4 = (tid2 >> 7) * 4;
        float bv = bias2s[gB];
        bv2 = pack2(bv, bv);
    }

    // ---- pipelined main loop: 17 iterations ----
    // iter i: group A runs LSTM1 step t=i (i<16), group B runs LSTM2 step t=i-1 (i>=1)
    int cur = 0;
    for (int i = 0; i < 17; ++i) {
        if (tid < 256) {
            if (i < 16) {
                // GEMV1: gates for 8 batches
                float pt = pt1s[i * 256 + tid];
                u64 pt2 = pack2(pt, pt);
                const ulonglong2* xp = (const ulonglong2*)&xs[i * 8];
                ulonglong2 x01 = xp[0], x23 = xp[1];
                u64 a0 = fma2(we12, x01.x, pt2);
                u64 a1 = fma2(we12, x01.y, pt2);
                u64 a2 = fma2(we12, x23.x, pt2);
                u64 a3 = fma2(we12, x23.y, pt2);
                const float* hb = h1s + cur * 512;
                #pragma unroll
                for (int k = 0; k < 64; k++) {
                    u64 wp = pack2(u1row[k], u1row[k]);
                    ulonglong2 hA = *(const ulonglong2*)&hb[k * 8];
                    ulonglong2 hB = *(const ulonglong2*)&hb[k * 8 + 4];
                    a0 = fma2(wp, hA.x, a0);
                    a1 = fma2(wp, hA.y, a1);
                    a2 = fma2(wp, hB.x, a2);
                    a3 = fma2(wp, hB.y, a3);
                }
                float f0, f1;
                unpack2(a0, f0, f1); g1s[0 * 256 + tid] = f0; g1s[1 * 256 + tid] = f1;
                unpack2(a1, f0, f1); g1s[2 * 256 + tid] = f0; g1s[3 * 256 + tid] = f1;
                unpack2(a2, f0, f1); g1s[4 * 256 + tid] = f0; g1s[5 * 256 + tid] = f1;
                unpack2(a3, f0, f1); g1s[6 * 256 + tid] = f0; g1s[7 * 256 + tid] = f1;

                asm volatile("bar.sync 1, 256;" ::: "memory");

                // cell update: 2 cells/thread, write h1 next buffer
                float* hn = h1s + (cur ^ 1) * 512;
                {
                    int b = tid >> 6, j = tid & 63;
                    float gi = g1s[b * 256 + j];
                    float gf = g1s[b * 256 + 64 + j];
                    float gg = g1s[b * 256 + 128 + j];
                    float go = g1s[b * 256 + 192 + j];
                    float nc = sigf(gf) * c1r0 + sigf(gi) * tanh_f(gg);
                    c1r0 = nc;
                    hn[j * 8 + b] = sigf(go) * tanh_f(nc);
                }
                {
                    int id = 256 + tid;
                    int b = id >> 6, j = id & 63;
                    float gi = g1s[b * 256 + j];
                    float gf = g1s[b * 256 + 64 + j];
                    float gg = g1s[b * 256 + 128 + j];
                    float go = g1s[b * 256 + 192 + j];
                    float nc = sigf(gf) * c1r1 + sigf(gi) * tanh_f(gg);
                    c1r1 = nc;
                    hn[j * 8 + b] = sigf(go) * tanh_f(nc);
                }
            }
        } else {
            if (i >= 1) {
                // GEMV2: 1 gate x 4 batches
                u64 a0 = bv2, a1 = bv2;
                const float* hb = h1s + cur * 512;
                #pragma unroll
                for (int k = 0; k < 64; k++) {
                    u64 wp = wih2p[k * 128 + gB];
                    ulonglong2 hA = *(const ulonglong2*)&hb[k * 8 + bg4];
                    a0 = fma2(wp, hA.x, a0);
                    a1 = fma2(wp, hA.y, a1);
                }
                #pragma unroll
                for (int k = 0; k < 32; k++) {
                    u64 wp = whh2p[k * 128 + gB];
                    ulonglong2 hA = *(const ulonglong2*)&h2s[k * 8 + bg4];
                    a0 = fma2(wp, hA.x, a0);
                    a1 = fma2(wp, hA.y, a1);
                }
                float f0, f1;
                unpack2(a0, f0, f1); g2s[(bg4 + 0) * 128 + gB] = f0; g2s[(bg4 + 1) * 128 + gB] = f1;
                unpack2(a1, f0, f1); g2s[(bg4 + 2) * 128 + gB] = f0; g2s[(bg4 + 3) * 128 + gB] = f1;

                asm volatile("bar.sync 2, 256;" ::: "memory");

                // cell update: 1 cell/thread
                int tid2 = tid - 256;
                int b = tid2 >> 5, j = tid2 & 31;
                float gi = g2s[b * 128 + j];
                float gf = g2s[b * 128 + 32 + j];
                float gg = g2s[b * 128 + 64 + j];
                float go = g2s[b * 128 + 96 + j];
                float nc = sigf(gf) * c2r + sigf(gi) * tanh_f(gg);
                c2r = nc;
                h2s[j * 8 + b] = sigf(go) * tanh_f(nc);
            }
        }
        __syncthreads();
        cur ^= 1;
    }

    // ---- qkv projection of l2_final = h2(15) + h1(15)[:32] ----
    // h1(15) lives in buffer 0 (written at iter 15 with cur=1 -> nxt=0)
    const float* h1f = h1s;
    #pragma unroll
    for (int r = 0; r < 2; ++r) {
        int oi = r * 512 + tid;
        if (oi < 768) {
            int b = oi / 96, g = oi % 96;
            float acc = attn_b[g];
            #pragma unroll 8
            for (int e = 0; e < 32; e++) {
                float vv = h2s[e * 8 + b] + h1f[e * 8 + b];
                acc = fmaf(vv, attn_w[g * 32 + e], acc);
            }
            int m = b0 + b;
            int head = (g & 31) >> 3;
            int d = g & 7;
            if (g < 32)      q_g[head * 8192 + m * 8 + d] = acc * 0.3535533905932738f;
            else if (g < 64) k_g[head * 8192 + m * 8 + d] = acc;
            else             v_g[head * 8192 + m * 8 + d] = acc;
        }
    }
}

// =====================================================================
// Kernel 2: attention across the 1024 batch dim. One head per blockIdx.y,
//           warp per output row, single fused pass (no max subtraction —
//           scores are O(1) here), float4 k/v.
// =====================================================================
__global__ void __launch_bounds__(256, 1) attn_kernel()
{
    extern __shared__ __align__(16) float sm[];
    float4* kh = (float4*)sm;          // [1024][8] floats = 2048 float4
    float4* vh = kh + 2048;

    const int head = blockIdx.y;
    const int tid = threadIdx.x, lane = tid & 31, w = tid >> 5;

    const float4* kg = (const float4*)(k_g + head * 8192);
    const float4* vg = (const float4*)(v_g + head * 8192);
    for (int i = tid; i < 2048; i += 256) { kh[i] = kg[i]; vh[i] = vg[i]; }
    __syncthreads();

    #pragma unroll
    for (int il = 0; il < 4; ++il) {
        int l = blockIdx.x * 32 + w * 4 + il;
        const float4* qp = (const float4*)(q_g + head * 8192 + l * 8);
        float4 q0 = qp[0], q1 = qp[1];

        float sum = 0.f;
        float acc[8];
        #pragma unroll
        for (int d = 0; d < 8; d++) acc[d] = 0.f;

        for (int m = lane; m < 1024; m += 32) {
            float4 kA = kh[m * 2], kB = kh[m * 2 + 1];
            float s = q0.x * kA.x;
            s = fmaf(q0.y, kA.y, s);
            s = fmaf(q0.z, kA.z, s);
            s = fmaf(q0.w, kA.w, s);
            s = fmaf(q1.x, kB.x, s);
            s = fmaf(q1.y, kB.y, s);
            s = fmaf(q1.z, kB.z, s);
            s = fmaf(q1.w, kB.w, s);
            float e = __expf(s);
            sum += e;
            float4 vA = vh[m * 2], vB = vh[m * 2 + 1];
            acc[0] = fmaf(e, vA.x, acc[0]);
            acc[1] = fmaf(e, vA.y, acc[1]);
            acc[2] = fmaf(e, vA.z, acc[2]);
            acc[3] = fmaf(e, vA.w, acc[3]);
            acc[4] = fmaf(e, vB.x, acc[4]);
            acc[5] = fmaf(e, vB.y, acc[5]);
            acc[6] = fmaf(e, vB.z, acc[6]);
            acc[7] = fmaf(e, vB.w, acc[7]);
        }
        #pragma unroll
        for (int o = 16; o > 0; o >>= 1) {
            sum += __shfl_xor_sync(0xffffffffu, sum, o);
            #pragma unroll
            for (int d = 0; d < 8; d++) acc[d] += __shfl_xor_sync(0xffffffffu, acc[d], o);
        }
        if (lane == 0) {
            float inv = 1.f / sum;
            #pragma unroll
            for (int d = 0; d < 8; d++) attn_g[l * 32 + head * 8 + d] = acc[d] * inv;
        }
    }
}

// =====================================================================
// Kernel 3: attn output proj + dense(32->64)+bn+relu + dense(64->32)+bn+relu
//           + dense(32->1) + sigmoid. 32 blocks x 32 batch each.
// =====================================================================
__global__ void __launch_bounds__(256, 1) mlp_kernel(
    const float* __restrict__ ow, const float* __restrict__ ob,
    const float* __restrict__ d1w, const float* __restrict__ d1b,
    const float* __restrict__ bg1, const float* __restrict__ bb1,
    const float* __restrict__ d2w, const float* __restrict__ d2b,
    const float* __restrict__ bg2, const float* __restrict__ bb2,
    const float* __restrict__ d3w, const float* __restrict__ d3b,
    float* __restrict__ out)
{
    __shared__ float owT[1024], d1T[2048], d2T[2048], d3s[32];
    __shared__ float obs[32], d1bs[64], d2bs[32], s1[64], sb1[64], s2[32], sb2[32];
    __shared__ float att[32 * 32], z1[32 * 32], z2[32 * 64], z3[32 * 32];

    const int tid = threadIdx.x;
    const int bb = blockIdx.x * 32;
    const float bnscale = rsqrtf(1.f + 1e-5f);

    for (int i = tid; i < 1024; i += 256) { int o = i & 31, e = i >> 5; owT[e * 32 + o] = ow[o * 32 + e]; }
    for (int i = tid; i < 2048; i += 256) { int o = i & 63, e = i >> 6; d1T[e * 64 + o] = d1w[o * 32 + e]; }
    for (int i = tid; i < 2048; i += 256) { int o = i & 31, e = i >> 5; d2T[e * 32 + o] = d2w[o * 64 + e]; }
    if (tid < 32) { d3s[tid] = d3w[tid]; obs[tid] = ob[tid]; d2bs[tid] = d2b[tid]; s2[tid] = bg2[tid] * bnscale; sb2[tid] = bb2[tid]; }
    if (tid < 64) { d1bs[tid] = d1b[tid]; s1[tid] = bg1[tid] * bnscale; sb1[tid] = bb1[tid]; }
    for (int i = tid; i < 1024; i += 256) att[i] = attn_g[bb * 32 + i];
    __syncthreads();

    for (int i = tid; i < 1024; i += 256) {
        int b = i >> 5, o = i & 31;
        float a = obs[o];
        #pragma unroll 8
        for (int e = 0; e < 32; e++) a += att[b * 32 + e] * owT[e * 32 + o];
        z1[b * 32 + o] = a;
    }
    __syncthreads();

    for (int i = tid; i < 2048; i += 256) {
        int b = i >> 6, o = i & 63;
        float a = d1bs[o];
        #pragma unroll 8
        for (int e = 0; e < 32; e++) a += z1[b * 32 + e] * d1T[e * 64 + o];
        a = a * s1[o] + sb1[o];
        z2[b * 64 + o] = fmaxf(a, 0.f);
    }
    __syncthreads();

    for (int i = tid; i < 1024; i += 256) {
        int b = i >> 5, o = i & 31;
        float a = d2bs[o];
        #pragma unroll 8
        for (int e = 0; e < 64; e++) a += z2[b * 64 + e] * d2T[e * 32 + o];
        a = a * s2[o] + sb2[o];
        z3[o * 32 + b] = fmaxf(a, 0.f);
    }
    __syncthreads();

    if (tid < 32) {
        int b = tid;
        float a = d3b[0];
        #pragma unroll 8
        for (int e = 0; e < 32; e++) a += z3[e * 32 + b] * d3s[e];
        out[bb + b] = 1.f / (1.f + __expf(-a));
    }
}

// =====================================================================
extern "C" void kernel_launch(void* const* d_in, const int* in_sizes, int n_in,
                              void* d_out, int out_size)
{
    const float* x      = (const float*)d_in[0];
    const float* emb_w  = (const float*)d_in[1];
    const float* emb_b  = (const float*)d_in[2];
    const float* l1_wih = (const float*)d_in[3];
    const float* l1_whh = (const float*)d_in[4];
    const float* l1_bih = (const float*)d_in[5];
    const float* l1_bhh = (const float*)d_in[6];
    const float* l2_wih = (const float*)d_in[7];
    const float* l2_whh = (const float*)d_in[8];
    const float* l2_bih = (const float*)d_in[9];
    const float* l2_bhh = (const float*)d_in[10];
    const float* attn_w = (const float*)d_in[11];
    const float* attn_b = (const float*)d_in[12];
    const float* attn_ow = (const float*)d_in[13];
    const float* attn_ob = (const float*)d_in[14];
    const float* d1_w   = (const float*)d_in[15];
    const float* d1_b   = (const float*)d_in[16];
    const float* bn1_g  = (const float*)d_in[17];
    const float* bn1_b  = (const float*)d_in[18];
    const float* d2_w   = (const float*)d_in[19];
    const float* d2_b   = (const float*)d_in[20];
    const float* bn2_g  = (const float*)d_in[21];
    const float* bn2_b  = (const float*)d_in[22];
    const float* d3_w   = (const float*)d_in[23];
    const float* d3_b   = (const float*)d_in[24];
    float* out = (float*)d_out;

    // smem: 12288 u64 (96KB) + 9280 floats (~36.3KB)
    const int smem1 = 12288 * 8 + 9280 * 4;        // 135,424 B
    const int smem2 = 4096 * 4 * 4;                 // 65,536 B (k+v float4)
    cudaFuncSetAttribute(lstm_kernel, cudaFuncAttributeMaxDynamicSharedMemorySize, smem1);
    cudaFuncSetAttribute(attn_kernel, cudaFuncAttributeMaxDynamicSharedMemorySize, smem2);

    lstm_kernel<<<128, 512, smem1>>>(x, emb_w, emb_b,
                                     l1_wih, l1_whh, l1_bih, l1_bhh,
                                     l2_wih, l2_whh, l2_bih, l2_bhh,
                                     attn_w, attn_b);
    attn_kernel<<<dim3(32, 4), 256, smem2>>>();
    mlp_kernel<<<32, 256>>>(attn_ow, attn_ob, d1_w, d1_b, bn1_g, bn1_b,
                            d2_w, d2_b, bn2_g, bn2_b, d3_w, d3_b, out);
}

// round 4
// speedup vs baseline: 1.1963x; 1.1963x over previous
#include <cuda_runtime.h>
#include <math.h>

// ---------------- global scratch (no allocations allowed) ----------------
__device__ float q_g[4 * 1024 * 8];
__device__ float k_g[4 * 1024 * 8];
__device__ float v_g[4 * 1024 * 8];
__device__ float attn_g[1024 * 32];

typedef unsigned long long u64;

__device__ __forceinline__ float tanh_f(float x) {
    float y; asm("tanh.approx.f32 %0, %1;" : "=f"(y) : "f"(x)); return y;
}
__device__ __forceinline__ float sigf(float x) {
    return fmaf(0.5f, tanh_f(0.5f * x), 0.5f);
}
__device__ __forceinline__ u64 pack2(float a, float b) {
    u64 r; asm("mov.b64 %0, {%1,%2};" : "=l"(r) : "f"(a), "f"(b)); return r;
}
__device__ __forceinline__ void unpack2(u64 v, float& a, float& b) {
    asm("mov.b64 {%0,%1}, %2;" : "=f"(a), "=f"(b) : "l"(v));
}
__device__ __forceinline__ u64 fma2(u64 a, u64 b, u64 c) {
    u64 d; asm("fma.rn.f32x2 %0, %1, %2, %3;" : "=l"(d) : "l"(a), "l"(b), "l"(c)); return d;
}

// =====================================================================
// Kernel 1: pipelined LSTM1 + LSTM2 with k-split GEMVs.
//   threads 0-511  : LSTM1 — gate g=tid&255, k-half hf=tid>>8 (32 iters)
//   threads 512-767: LSTM2 — gate g=t2&127,  k-half hf=t2>>7 (48 iters)
//   128 CTAs x 768 threads, 8 batch rows per CTA.
// =====================================================================
__global__ void __launch_bounds__(768, 1) lstm_kernel(
    const float* __restrict__ x,
    const float* __restrict__ emb_w, const float* __restrict__ emb_b,
    const float* __restrict__ w1, const float* __restrict__ u1,
    const float* __restrict__ b1i, const float* __restrict__ b1h,
    const float* __restrict__ w2, const float* __restrict__ u2,
    const float* __restrict__ b2i, const float* __restrict__ b2h,
    const float* __restrict__ attn_w, const float* __restrict__ attn_b)
{
    extern __shared__ __align__(16) float sm[];
    float* pt1s   = sm;              // [16][256]  4096
    float* pe     = pt1s + 4096;     // [16][32]    512
    float* embw_s = pe + 512;        // 32
    float* embb_s = embw_s + 32;     // 32
    float* xs     = embb_s + 32;     // [16][8]     128
    float* h1s    = xs + 128;        // 2 x [64][8] 1024
    float* h2s    = h1s + 1024;      // [32][8]     256
    float* g1p    = h2s + 256;       // [2][8][256] 4096
    float* g2p    = g1p + 4096;      // [2][8][128] 2048

    const int tid = threadIdx.x;
    const int b0 = blockIdx.x * 8;

    // ---- shared prologue ----
    if (tid < 512) {
        int t = tid >> 5, e = tid & 31;
        int half = e >> 1;
        float div = __expf(-(float)(2 * half) * (9.210340371976184f / 32.0f));
        float arg = (float)t * div;
        pe[tid] = (e & 1) ? cosf(arg) : sinf(arg);
    }
    if (tid < 32) { embw_s[tid] = emb_w[tid]; embb_s[tid] = emb_b[tid]; }
    if (tid < 128) { int t = tid >> 3, b = tid & 7; xs[tid] = x[(b0 + b) * 16 + t]; }
    if (tid < 512) h1s[tid] = 0.f;          // buffer 0
    if (tid >= 512) h2s[tid - 512] = 0.f;   // 256 floats
    __syncthreads();

    // ---- per-thread register setup ----
    float wreg[48];
    u64 we12 = 0, bv2 = 0;
    float c1r = 0.f, c2r = 0.f;
    int gA = 0, hfA = 0, gB = 0, hfB = 0;

    if (tid < 512) {
        gA = tid & 255; hfA = tid >> 8;
        if (hfA == 0) {
            float w1r[32];
            const float4* w1p = (const float4*)(w1 + gA * 32);
            #pragma unroll
            for (int q = 0; q < 8; q++) {
                float4 v = w1p[q];
                w1r[q*4+0]=v.x; w1r[q*4+1]=v.y; w1r[q*4+2]=v.z; w1r[q*4+3]=v.w;
            }
            float we1 = 0.f, wb = b1i[gA] + b1h[gA];
            #pragma unroll
            for (int e = 0; e < 32; e++) {
                we1 = fmaf(w1r[e], embw_s[e], we1);
                wb  = fmaf(w1r[e], embb_s[e], wb);
            }
            we12 = pack2(we1, we1);
            #pragma unroll
            for (int t = 0; t < 16; t++) {
                float s = wb;
                #pragma unroll
                for (int e = 0; e < 32; e++) s = fmaf(w1r[e], pe[t * 32 + e], s);
                pt1s[t * 256 + gA] = s;
            }
        }
        // my half of the LSTM1 recurrent row
        const float4* up = (const float4*)(u1 + gA * 64 + hfA * 32);
        #pragma unroll
        for (int q = 0; q < 8; q++) {
            float4 v = up[q];
            wreg[q*4+0]=v.x; wreg[q*4+1]=v.y; wreg[q*4+2]=v.z; wreg[q*4+3]=v.w;
        }
    } else {
        int t2 = tid - 512;
        gB = t2 & 127; hfB = t2 >> 7;
        if (hfB == 0) {
            const float4* p = (const float4*)(w2 + gB * 64);
            #pragma unroll
            for (int q = 0; q < 12; q++) {
                float4 v = p[q];
                wreg[q*4+0]=v.x; wreg[q*4+1]=v.y; wreg[q*4+2]=v.z; wreg[q*4+3]=v.w;
            }
            float bv = b2i[gB] + b2h[gB];
            bv2 = pack2(bv, bv);
        } else {
            const float4* p = (const float4*)(w2 + gB * 64 + 48);
            #pragma unroll
            for (int q = 0; q < 4; q++) {
                float4 v = p[q];
                wreg[q*4+0]=v.x; wreg[q*4+1]=v.y; wreg[q*4+2]=v.z; wreg[q*4+3]=v.w;
            }
            const float4* p2 = (const float4*)(u2 + gB * 32);
            #pragma unroll
            for (int q = 0; q < 8; q++) {
                float4 v = p2[q];
                wreg[16+q*4+0]=v.x; wreg[16+q*4+1]=v.y; wreg[16+q*4+2]=v.z; wreg[16+q*4+3]=v.w;
            }
        }
    }

    // ---- pipelined main loop: 17 iterations ----
    // iter i: LSTM1 runs step t=i (i<16), LSTM2 runs step t=i-1 (i>=1)
    int cur = 0;
    for (int i = 0; i < 17; ++i) {
        const float* hb = h1s + cur * 512;
        if (tid < 512) {
            if (i < 16) {
                u64 a0, a1, a2, a3;
                if (hfA == 0) {
                    float pt = pt1s[i * 256 + gA];
                    u64 pt2 = pack2(pt, pt);
                    const ulonglong2* xp = (const ulonglong2*)&xs[i * 8];
                    ulonglong2 x01 = xp[0], x23 = xp[1];
                    a0 = fma2(we12, x01.x, pt2);
                    a1 = fma2(we12, x01.y, pt2);
                    a2 = fma2(we12, x23.x, pt2);
                    a3 = fma2(we12, x23.y, pt2);
                } else { a0 = a1 = a2 = a3 = 0ULL; }
                const float* hk = hb + hfA * 256;
                #pragma unroll
                for (int k = 0; k < 32; k++) {
                    u64 wp = pack2(wreg[k], wreg[k]);
                    ulonglong2 hA = *(const ulonglong2*)&hk[k * 8];
                    ulonglong2 hB = *(const ulonglong2*)&hk[k * 8 + 4];
                    a0 = fma2(wp, hA.x, a0);
                    a1 = fma2(wp, hA.y, a1);
                    a2 = fma2(wp, hB.x, a2);
                    a3 = fma2(wp, hB.y, a3);
                }
                float f0, f1;
                float* gp = g1p + hfA * 2048 + gA;
                unpack2(a0, f0, f1); gp[0]    = f0; gp[256]  = f1;
                unpack2(a1, f0, f1); gp[512]  = f0; gp[768]  = f1;
                unpack2(a2, f0, f1); gp[1024] = f0; gp[1280] = f1;
                unpack2(a3, f0, f1); gp[1536] = f0; gp[1792] = f1;

                asm volatile("bar.sync 1, 512;" ::: "memory");

                // cell update: one cell per thread
                int b = tid >> 6, j = tid & 63;
                const float* p0 = g1p + b * 256 + j;
                const float* p1 = p0 + 2048;
                float gi = p0[0]   + p1[0];
                float gf = p0[64]  + p1[64];
                float gg = p0[128] + p1[128];
                float go = p0[192] + p1[192];
                float nc = sigf(gf) * c1r + sigf(gi) * tanh_f(gg);
                c1r = nc;
                float* hn = h1s + (cur ^ 1) * 512;
                hn[j * 8 + b] = sigf(go) * tanh_f(nc);
            }
        } else {
            if (i >= 1) {
                int t2 = tid - 512;
                u64 a0, a1, a2, a3;
                if (hfB == 0) {
                    a0 = a1 = a2 = a3 = bv2;
                    #pragma unroll
                    for (int k = 0; k < 48; k++) {
                        u64 wp = pack2(wreg[k], wreg[k]);
                        ulonglong2 hA = *(const ulonglong2*)&hb[k * 8];
                        ulonglong2 hB = *(const ulonglong2*)&hb[k * 8 + 4];
                        a0 = fma2(wp, hA.x, a0);
                        a1 = fma2(wp, hA.y, a1);
                        a2 = fma2(wp, hB.x, a2);
                        a3 = fma2(wp, hB.y, a3);
                    }
                } else {
                    a0 = a1 = a2 = a3 = 0ULL;
                    #pragma unroll
                    for (int k = 0; k < 16; k++) {  // h1 rows 48..63
                        u64 wp = pack2(wreg[k], wreg[k]);
                        ulonglong2 hA = *(const ulonglong2*)&hb[(48 + k) * 8];
                        ulonglong2 hB = *(const ulonglong2*)&hb[(48 + k) * 8 + 4];
                        a0 = fma2(wp, hA.x, a0);
                        a1 = fma2(wp, hA.y, a1);
                        a2 = fma2(wp, hB.x, a2);
                        a3 = fma2(wp, hB.y, a3);
                    }
                    #pragma unroll
                    for (int k = 0; k < 32; k++) {  // h2 rows
                        u64 wp = pack2(wreg[16 + k], wreg[16 + k]);
                        ulonglong2 hA = *(const ulonglong2*)&h2s[k * 8];
                        ulonglong2 hB = *(const ulonglong2*)&h2s[k * 8 + 4];
                        a0 = fma2(wp, hA.x, a0);
                        a1 = fma2(wp, hA.y, a1);
                        a2 = fma2(wp, hB.x, a2);
                        a3 = fma2(wp, hB.y, a3);
                    }
                }
                float f0, f1;
                float* gp = g2p + hfB * 1024 + gB;
                unpack2(a0, f0, f1); gp[0]   = f0; gp[128] = f1;
                unpack2(a1, f0, f1); gp[256] = f0; gp[384] = f1;
                unpack2(a2, f0, f1); gp[512] = f0; gp[640] = f1;
                unpack2(a3, f0, f1); gp[768] = f0; gp[896] = f1;

                asm volatile("bar.sync 2, 256;" ::: "memory");

                // cell update: one cell per thread
                int b = t2 >> 5, j = t2 & 31;
                const float* p0 = g2p + b * 128 + j;
                const float* p1 = p0 + 1024;
                float gi = p0[0]  + p1[0];
                float gf = p0[32] + p1[32];
                float gg = p0[64] + p1[64];
                float go = p0[96] + p1[96];
                float nc = sigf(gf) * c2r + sigf(gi) * tanh_f(gg);
                c2r = nc;
                h2s[j * 8 + b] = sigf(go) * tanh_f(nc);
            }
        }
        __syncthreads();
        cur ^= 1;
    }

    // ---- qkv projection of l2_final = h2(15) + h1(15)[:32] ----
    // h1(15) lives in buffer 0 (written at iter 15 with cur=1 -> nxt=0)
    {
        int b = tid / 96, g = tid % 96;   // 768 = 8 * 96 exactly
        float acc = attn_b[g];
        #pragma unroll 8
        for (int e = 0; e < 32; e++) {
            float vv = h2s[e * 8 + b] + h1s[e * 8 + b];
            acc = fmaf(vv, attn_w[g * 32 + e], acc);
        }
        int m = b0 + b;
        int head = (g & 31) >> 3;
        int d = g & 7;
        if (g < 32)      q_g[head * 8192 + m * 8 + d] = acc * 0.3535533905932738f;
        else if (g < 64) k_g[head * 8192 + m * 8 + d] = acc;
        else             v_g[head * 8192 + m * 8 + d] = acc;
    }
}

// =====================================================================
// Kernel 2: attention across the 1024 batch dim. One head per blockIdx.y,
//           warp per output row, single fused pass, SoA float4 k/v
//           (conflict-free LDS.128).
// =====================================================================
__global__ void __launch_bounds__(256, 1) attn_kernel()
{
    extern __shared__ __align__(16) float smf[];
    float4* kA = (float4*)smf;     // [1024]
    float4* kB = kA + 1024;
    float4* vA = kB + 1024;
    float4* vB = vA + 1024;

    const int head = blockIdx.y;
    const int tid = threadIdx.x, lane = tid & 31, w = tid >> 5;

    const float4* kg = (const float4*)(k_g + head * 8192);
    const float4* vg = (const float4*)(v_g + head * 8192);
    for (int i = tid; i < 2048; i += 256) {
        float4 kv = kg[i], vv = vg[i];
        if (i & 1) { kB[i >> 1] = kv; vB[i >> 1] = vv; }
        else       { kA[i >> 1] = kv; vA[i >> 1] = vv; }
    }
    __syncthreads();

    #pragma unroll
    for (int il = 0; il < 4; ++il) {
        int l = blockIdx.x * 32 + w * 4 + il;
        const float4* qp = (const float4*)(q_g + head * 8192 + l * 8);
        float4 q0 = qp[0], q1 = qp[1];

        float sum = 0.f;
        float acc[8];
        #pragma unroll
        for (int d = 0; d < 8; d++) acc[d] = 0.f;

        for (int m = lane; m < 1024; m += 32) {
            float4 ka = kA[m], kb = kB[m];
            float s = q0.x * ka.x;
            s = fmaf(q0.y, ka.y, s);
            s = fmaf(q0.z, ka.z, s);
            s = fmaf(q0.w, ka.w, s);
            s = fmaf(q1.x, kb.x, s);
            s = fmaf(q1.y, kb.y, s);
            s = fmaf(q1.z, kb.z, s);
            s = fmaf(q1.w, kb.w, s);
            float e = __expf(s);
            sum += e;
            float4 va = vA[m], vb = vB[m];
            acc[0] = fmaf(e, va.x, acc[0]);
            acc[1] = fmaf(e, va.y, acc[1]);
            acc[2] = fmaf(e, va.z, acc[2]);
            acc[3] = fmaf(e, va.w, acc[3]);
            acc[4] = fmaf(e, vb.x, acc[4]);
            acc[5] = fmaf(e, vb.y, acc[5]);
            acc[6] = fmaf(e, vb.z, acc[6]);
            acc[7] = fmaf(e, vb.w, acc[7]);
        }
        #pragma unroll
        for (int o = 16; o > 0; o >>= 1) {
            sum += __shfl_xor_sync(0xffffffffu, sum, o);
            #pragma unroll
            for (int d = 0; d < 8; d++) acc[d] += __shfl_xor_sync(0xffffffffu, acc[d], o);
        }
        if (lane == 0) {
            float inv = 1.f / sum;
            #pragma unroll
            for (int d = 0; d < 8; d++) attn_g[l * 32 + head * 8 + d] = acc[d] * inv;
        }
    }
}

// =====================================================================
// Kernel 3: attn output proj + dense(32->64)+bn+relu + dense(64->32)+bn+relu
//           + dense(32->1) + sigmoid. 32 blocks x 32 batch each.
// =====================================================================
__global__ void __launch_bounds__(256, 1) mlp_kernel(
    const float* __restrict__ ow, const float* __restrict__ ob,
    const float* __restrict__ d1w, const float* __restrict__ d1b,
    const float* __restrict__ bg1, const float* __restrict__ bb1,
    const float* __restrict__ d2w, const float* __restrict__ d2b,
    const float* __restrict__ bg2, const float* __restrict__ bb2,
    const float* __restrict__ d3w, const float* __restrict__ d3b,
    float* __restrict__ out)
{
    __shared__ float owT[1024], d1T[2048], d2T[2048], d3s[32];
    __shared__ float obs[32], d1bs[64], d2bs[32], s1[64], sb1[64], s2[32], sb2[32];
    __shared__ float att[32 * 32], z1[32 * 32], z2[32 * 64], z3[32 * 32];

    const int tid = threadIdx.x;
    const int bb = blockIdx.x * 32;
    const float bnscale = rsqrtf(1.f + 1e-5f);

    for (int i = tid; i < 1024; i += 256) { int o = i & 31, e = i >> 5; owT[e * 32 + o] = ow[o * 32 + e]; }
    for (int i = tid; i < 2048; i += 256) { int o = i & 63, e = i >> 6; d1T[e * 64 + o] = d1w[o * 32 + e]; }
    for (int i = tid; i < 2048; i += 256) { int o = i & 31, e = i >> 5; d2T[e * 32 + o] = d2w[o * 64 + e]; }
    if (tid < 32) { d3s[tid] = d3w[tid]; obs[tid] = ob[tid]; d2bs[tid] = d2b[tid]; s2[tid] = bg2[tid] * bnscale; sb2[tid] = bb2[tid]; }
    if (tid < 64) { d1bs[tid] = d1b[tid]; s1[tid] = bg1[tid] * bnscale; sb1[tid] = bb1[tid]; }
    for (int i = tid; i < 1024; i += 256) att[i] = attn_g[bb * 32 + i];
    __syncthreads();

    for (int i = tid; i < 1024; i += 256) {
        int b = i >> 5, o = i & 31;
        float a = obs[o];
        #pragma unroll 8
        for (int e = 0; e < 32; e++) a += att[b * 32 + e] * owT[e * 32 + o];
        z1[b * 32 + o] = a;
    }
    __syncthreads();

    for (int i = tid; i < 2048; i += 256) {
        int b = i >> 6, o = i & 63;
        float a = d1bs[o];
        #pragma unroll 8
        for (int e = 0; e < 32; e++) a += z1[b * 32 + e] * d1T[e * 64 + o];
        a = a * s1[o] + sb1[o];
        z2[b * 64 + o] = fmaxf(a, 0.f);
    }
    __syncthreads();

    for (int i = tid; i < 1024; i += 256) {
        int b = i >> 5, o = i & 31;
        float a = d2bs[o];
        #pragma unroll 8
        for (int e = 0; e < 64; e++) a += z2[b * 64 + e] * d2T[e * 32 + o];
        a = a * s2[o] + sb2[o];
        z3[o * 32 + b] = fmaxf(a, 0.f);
    }
    __syncthreads();

    if (tid < 32) {
        int b = tid;
        float a = d3b[0];
        #pragma unroll 8
        for (int e = 0; e < 32; e++) a += z3[e * 32 + b] * d3s[e];
        out[bb + b] = 1.f / (1.f + __expf(-a));
    }
}

// =====================================================================
extern "C" void kernel_launch(void* const* d_in, const int* in_sizes, int n_in,
                              void* d_out, int out_size)
{
    const float* x      = (const float*)d_in[0];
    const float* emb_w  = (const float*)d_in[1];
    const float* emb_b  = (const float*)d_in[2];
    const float* l1_wih = (const float*)d_in[3];
    const float* l1_whh = (const float*)d_in[4];
    const float* l1_bih = (const float*)d_in[5];
    const float* l1_bhh = (const float*)d_in[6];
    const float* l2_wih = (const float*)d_in[7];
    const float* l2_whh = (const float*)d_in[8];
    const float* l2_bih = (const float*)d_in[9];
    const float* l2_bhh = (const float*)d_in[10];
    const float* attn_w = (const float*)d_in[11];
    const float* attn_b = (const float*)d_in[12];
    const float* attn_ow = (const float*)d_in[13];
    const float* attn_ob = (const float*)d_in[14];
    const float* d1_w   = (const float*)d_in[15];
    const float* d1_b   = (const float*)d_in[16];
    const float* bn1_g  = (const float*)d_in[17];
    const float* bn1_b  = (const float*)d_in[18];
    const float* d2_w   = (const float*)d_in[19];
    const float* d2_b   = (const float*)d_in[20];
    const float* bn2_g  = (const float*)d_in[21];
    const float* bn2_b  = (const float*)d_in[22];
    const float* d3_w   = (const float*)d_in[23];
    const float* d3_b   = (const float*)d_in[24];
    float* out = (float*)d_out;

    const int smem1 = 12224 * 4;      // 48,896 B
    const int smem2 = 4096 * 16;      // 65,536 B
    cudaFuncSetAttribute(lstm_kernel, cudaFuncAttributeMaxDynamicSharedMemorySize, smem1);
    cudaFuncSetAttribute(attn_kernel, cudaFuncAttributeMaxDynamicSharedMemorySize, smem2);

    lstm_kernel<<<128, 768, smem1>>>(x, emb_w, emb_b,
                                     l1_wih, l1_whh, l1_bih, l1_bhh,
                                     l2_wih, l2_whh, l2_bih, l2_bhh,
                                     attn_w, attn_b);
    attn_kernel<<<dim3(32, 4), 256, smem2>>>();
    mlp_kernel<<<32, 256>>>(attn_ow, attn_ob, d1_w, d1_b, bn1_g, bn1_b,
                            d2_w, d2_b, bn2_g, bn2_b, d3_w, d3_b, out);
}

// round 5
// speedup vs baseline: 1.2600x; 1.0533x over previous
#include <cuda_runtime.h>
#include <math.h>

// ---------------- global scratch (no allocations allowed) ----------------
__device__ float q_g[4 * 1024 * 8];
__device__ float k_g[4 * 1024 * 8];
__device__ float v_g[4 * 1024 * 8];
__device__ float accp_g[1024 * 4 * 4 * 8];   // [l][head][quarter][8]
__device__ float sump_g[1024 * 4 * 4];       // [l][head][quarter]

typedef unsigned long long u64;

__device__ __forceinline__ float tanh_f(float x) {
    float y; asm("tanh.approx.f32 %0, %1;" : "=f"(y) : "f"(x)); return y;
}
__device__ __forceinline__ float sigf(float x) {
    return fmaf(0.5f, tanh_f(0.5f * x), 0.5f);
}
__device__ __forceinline__ u64 pack2(float a, float b) {
    u64 r; asm("mov.b64 %0, {%1,%2};" : "=l"(r) : "f"(a), "f"(b)); return r;
}
__device__ __forceinline__ void unpack2(u64 v, float& a, float& b) {
    asm("mov.b64 {%0,%1}, %2;" : "=f"(a), "=f"(b) : "l"(v));
}
__device__ __forceinline__ u64 fma2(u64 a, u64 b, u64 c) {
    u64 d; asm("fma.rn.f32x2 %0, %1, %2, %3;" : "=l"(d) : "l"(a), "l"(b), "l"(c)); return d;
}

// =====================================================================
// Kernel 1: pipelined LSTM1 + LSTM2, 2 gates per thread, k-split GEMVs.
//   threads 0-511  : LSTM1 — gate pair p=tid&127 (gates 2p,2p+1),
//                    k-quarter q=tid>>7 (16 iters each)
//   threads 512-767: LSTM2 — gate pair p=t2&63, k-split s=t2>>6 covering
//                    rows s*24..s*24+23 of concat(h1[64],h2[32]) (24 iters)
//   128 CTAs x 768 threads, 8 batch rows per CTA.
// =====================================================================
__global__ void __launch_bounds__(768, 1) lstm_kernel(
    const float* __restrict__ x,
    const float* __restrict__ emb_w, const float* __restrict__ emb_b,
    const float* __restrict__ w1, const float* __restrict__ u1,
    const float* __restrict__ b1i, const float* __restrict__ b1h,
    const float* __restrict__ w2, const float* __restrict__ u2,
    const float* __restrict__ b2i, const float* __restrict__ b2h,
    const float* __restrict__ attn_w, const float* __restrict__ attn_b)
{
    extern __shared__ __align__(16) float sm[];
    float* g1p    = sm;              // [4][8][256]  8192
    float* g2p    = g1p + 8192;     // [4][8][128]  4096
    float* pt1s   = g2p + 4096;     // [16][256]    4096
    float* pe     = pt1s + 4096;    // [16][32]      512
    float* xs     = pe + 512;       // [16][8]       128
    float* hcat   = xs + 128;       // [2][96][8]   1536
    float* embw_s = hcat + 1536;    // 32
    float* embb_s = embw_s + 32;    // 32

    const int tid = threadIdx.x;
    const int b0 = blockIdx.x * 8;

    // ---- shared prologue ----
    if (tid < 512) {
        int t = tid >> 5, e = tid & 31;
        int half = e >> 1;
        float div = __expf(-(float)(2 * half) * (9.210340371976184f / 32.0f));
        float arg = (float)t * div;
        pe[tid] = (e & 1) ? cosf(arg) : sinf(arg);
    }
    if (tid < 32) { embw_s[tid] = emb_w[tid]; embb_s[tid] = emb_b[tid]; }
    if (tid < 128) { int t = tid >> 3, b = tid & 7; xs[tid] = x[(b0 + b) * 16 + t]; }
    for (int i = tid; i < 1536; i += 768) hcat[i] = 0.f;
    __syncthreads();

    // ---- pt1s + we1 (embedding folded into LSTM1): threads < 256, one gate each ----
    if (tid < 256) {
        int gate = 2 * (tid & 127) + (tid >> 7);
        float w1r[32];
        const float4* w1p = (const float4*)(w1 + gate * 32);
        #pragma unroll
        for (int qq = 0; qq < 8; qq++) {
            float4 v = w1p[qq];
            w1r[qq*4+0]=v.x; w1r[qq*4+1]=v.y; w1r[qq*4+2]=v.z; w1r[qq*4+3]=v.w;
        }
        float we1 = 0.f, wb = b1i[gate] + b1h[gate];
        #pragma unroll
        for (int e = 0; e < 32; e++) {
            we1 = fmaf(w1r[e], embw_s[e], we1);
            wb  = fmaf(w1r[e], embb_s[e], wb);
        }
        g1p[gate] = we1;   // stash
        #pragma unroll
        for (int t = 0; t < 16; t++) {
            float s = wb;
            #pragma unroll
            for (int e = 0; e < 32; e++) s = fmaf(w1r[e], pe[t * 32 + e], s);
            pt1s[t * 256 + gate] = s;
        }
    }
    __syncthreads();

    // ---- per-thread register setup ----
    float wreg[48];
    u64 weA = 0, weB = 0, bvA = 0, bvB = 0;
    float c1r = 0.f, c2r = 0.f;
    int pA = 0, qA = 0, pB = 0, sB = 0;

    if (tid < 512) {
        pA = tid & 127; qA = tid >> 7;
        const float4* a0 = (const float4*)(u1 + (2 * pA) * 64 + qA * 16);
        const float4* a1 = (const float4*)(u1 + (2 * pA + 1) * 64 + qA * 16);
        #pragma unroll
        for (int qq = 0; qq < 4; qq++) {
            float4 v = a0[qq];
            wreg[qq*4+0]=v.x; wreg[qq*4+1]=v.y; wreg[qq*4+2]=v.z; wreg[qq*4+3]=v.w;
            float4 u = a1[qq];
            wreg[16+qq*4+0]=u.x; wreg[16+qq*4+1]=u.y; wreg[16+qq*4+2]=u.z; wreg[16+qq*4+3]=u.w;
        }
        if (qA == 0) {
            float wa = g1p[2 * pA], wbv = g1p[2 * pA + 1];
            weA = pack2(wa, wa); weB = pack2(wbv, wbv);
        }
    } else {
        int t2 = tid - 512;
        pB = t2 & 63; sB = t2 >> 6;
        #pragma unroll
        for (int g = 0; g < 2; g++) {
            int row = 2 * pB + g;
            #pragma unroll
            for (int c = 0; c < 24; c++) {
                int r = sB * 24 + c;
                wreg[g * 24 + c] = (r < 64) ? w2[row * 64 + r] : u2[row * 32 + (r - 64)];
            }
        }
        if (sB == 0) {
            float ba = b2i[2 * pB] + b2h[2 * pB];
            float bb = b2i[2 * pB + 1] + b2h[2 * pB + 1];
            bvA = pack2(ba, ba); bvB = pack2(bb, bb);
        }
    }
    __syncthreads();   // stash in g1p consumed before main loop overwrites

    // ---- pipelined main loop: 17 iterations ----
    for (int i = 0; i < 17; ++i) {
        int cur = i & 1;
        const float* hc = hcat + cur * 768;
        float* hn = hcat + (cur ^ 1) * 768;
        if (tid < 512) {
            if (i < 16) {
                u64 a00, a01, a02, a03, a10, a11, a12, a13;
                if (qA == 0) {
                    float pt0 = pt1s[i * 256 + 2 * pA];
                    float pt1 = pt1s[i * 256 + 2 * pA + 1];
                    u64 p0 = pack2(pt0, pt0), p1 = pack2(pt1, pt1);
                    const ulonglong2* xp = (const ulonglong2*)&xs[i * 8];
                    ulonglong2 x01 = xp[0], x23 = xp[1];
                    a00 = fma2(weA, x01.x, p0); a01 = fma2(weA, x01.y, p0);
                    a02 = fma2(weA, x23.x, p0); a03 = fma2(weA, x23.y, p0);
                    a10 = fma2(weB, x01.x, p1); a11 = fma2(weB, x01.y, p1);
                    a12 = fma2(weB, x23.x, p1); a13 = fma2(weB, x23.y, p1);
                } else {
                    a00=a01=a02=a03=a10=a11=a12=a13=0ULL;
                }
                const float* hk = hc + qA * 128;
                #pragma unroll
                for (int k = 0; k < 16; k++) {
                    ulonglong2 hA = *(const ulonglong2*)&hk[k * 8];
                    ulonglong2 hB = *(const ulonglong2*)&hk[k * 8 + 4];
                    u64 w0 = pack2(wreg[k], wreg[k]);
                    a00 = fma2(w0, hA.x, a00); a01 = fma2(w0, hA.y, a01);
                    a02 = fma2(w0, hB.x, a02); a03 = fma2(w0, hB.y, a03);
                    u64 w1p = pack2(wreg[16 + k], wreg[16 + k]);
                    a10 = fma2(w1p, hA.x, a10); a11 = fma2(w1p, hA.y, a11);
                    a12 = fma2(w1p, hB.x, a12); a13 = fma2(w1p, hB.y, a13);
                }
                // store: g1p[q][b][gate]
                float f0, f1;
                float* gp0 = g1p + qA * 2048 + 2 * pA;
                unpack2(a00, f0, f1); gp0[0]    = f0; gp0[256]  = f1;
                unpack2(a01, f0, f1); gp0[512]  = f0; gp0[768]  = f1;
                unpack2(a02, f0, f1); gp0[1024] = f0; gp0[1280] = f1;
                unpack2(a03, f0, f1); gp0[1536] = f0; gp0[1792] = f1;
                float* gp1 = gp0 + 1;
                unpack2(a10, f0, f1); gp1[0]    = f0; gp1[256]  = f1;
                unpack2(a11, f0, f1); gp1[512]  = f0; gp1[768]  = f1;
                unpack2(a12, f0, f1); gp1[1024] = f0; gp1[1280] = f1;
                unpack2(a13, f0, f1); gp1[1536] = f0; gp1[1792] = f1;

                asm volatile("bar.sync 1, 512;" ::: "memory");

                // cell update: one cell per thread, sum 4 quarters
                int b = tid >> 6, j = tid & 63;
                const float* gp = g1p + b * 256 + j;
                float gi = gp[0]       + gp[2048]      + gp[4096]      + gp[6144];
                float gf = gp[64]      + gp[2048+64]   + gp[4096+64]   + gp[6144+64];
                float gg = gp[128]     + gp[2048+128]  + gp[4096+128]  + gp[6144+128];
                float go = gp[192]     + gp[2048+192]  + gp[4096+192]  + gp[6144+192];
                float nc = sigf(gf) * c1r + sigf(gi) * tanh_f(gg);
                c1r = nc;
                hn[j * 8 + b] = sigf(go) * tanh_f(nc);
            }
        } else {
            if (i >= 1) {
                int t2 = tid - 512;
                u64 a00, a01, a02, a03, a10, a11, a12, a13;
                if (sB == 0) { a00=a01=a02=a03=bvA; a10=a11=a12=a13=bvB; }
                else { a00=a01=a02=a03=a10=a11=a12=a13=0ULL; }
                const float* hk = hc + sB * 192;   // rows s*24.. of hcat
                #pragma unroll
                for (int c = 0; c < 24; c++) {
                    ulonglong2 hA = *(const ulonglong2*)&hk[c * 8];
                    ulonglong2 hB = *(const ulonglong2*)&hk[c * 8 + 4];
                    u64 w0 = pack2(wreg[c], wreg[c]);
                    a00 = fma2(w0, hA.x, a00); a01 = fma2(w0, hA.y, a01);
                    a02 = fma2(w0, hB.x, a02); a03 = fma2(w0, hB.y, a03);
                    u64 w1p = pack2(wreg[24 + c], wreg[24 + c]);
                    a10 = fma2(w1p, hA.x, a10); a11 = fma2(w1p, hA.y, a11);
                    a12 = fma2(w1p, hB.x, a12); a13 = fma2(w1p, hB.y, a13);
                }
                float f0, f1;
                float* gp0 = g2p + sB * 1024 + 2 * pB;
                unpack2(a00, f0, f1); gp0[0]   = f0; gp0[128] = f1;
                unpack2(a01, f0, f1); gp0[256] = f0; gp0[384] = f1;
                unpack2(a02, f0, f1); gp0[512] = f0; gp0[640] = f1;
                unpack2(a03, f0, f1); gp0[768] = f0; gp0[896] = f1;
                float* gp1 = gp0 + 1;
                unpack2(a10, f0, f1); gp1[0]   = f0; gp1[128] = f1;
                unpack2(a11, f0, f1); gp1[256] = f0; gp1[384] = f1;
                unpack2(a12, f0, f1); gp1[512] = f0; gp1[640] = f1;
                unpack2(a13, f0, f1); gp1[768] = f0; gp1[896] = f1;

                asm volatile("bar.sync 2, 256;" ::: "memory");

                // cell update: one cell per thread, sum 4 splits
                int b = t2 >> 5, j = t2 & 31;
                const float* gp = g2p + b * 128 + j;
                float gi = gp[0]    + gp[1024]    + gp[2048]    + gp[3072];
                float gf = gp[32]   + gp[1024+32] + gp[2048+32] + gp[3072+32];
                float gg = gp[64]   + gp[1024+64] + gp[2048+64] + gp[3072+64];
                float go = gp[96]   + gp[1024+96] + gp[2048+96] + gp[3072+96];
                float nc = sigf(gf) * c2r + sigf(gi) * tanh_f(gg);
                c2r = nc;
                hn[(64 + j) * 8 + b] = sigf(go) * tanh_f(nc);
            }
        }
        __syncthreads();
    }

    // ---- qkv projection of l2_final = h2(15) + h1(15)[:32] ----
    // h1(15) in hcat buffer 0 rows 0-63; h2(15) in hcat buffer 1 rows 64-95.
    {
        int b = tid / 96, g = tid % 96;   // 768 = 8 * 96 exactly
        float acc = attn_b[g];
        #pragma unroll 8
        for (int e = 0; e < 32; e++) {
            float vv = hcat[e * 8 + b] + hcat[768 + (64 + e) * 8 + b];
            acc = fmaf(vv, attn_w[g * 32 + e], acc);
        }
        int m = b0 + b;
        int head = (g & 31) >> 3;
        int d = g & 7;
        if (g < 32)      q_g[head * 8192 + m * 8 + d] = acc * 0.3535533905932738f;
        else if (g < 64) k_g[head * 8192 + m * 8 + d] = acc;
        else             v_g[head * 8192 + m * 8 + d] = acc;
    }
}

// =====================================================================
// Kernel 2: attention partials. grid (32 row-blocks, 4 heads, 4 m-quarters).
//           Each CTA: 32 q-rows x 256 keys, SoA float4 k/v in smem,
//           no max subtraction (scores are O(1)) so partials are additive.
// =====================================================================
__global__ void __launch_bounds__(256, 1) attn_kernel()
{
    __shared__ __align__(16) float4 kA[256], kB[256], vA[256], vB[256];

    const int head = blockIdx.y, z = blockIdx.z;
    const int tid = threadIdx.x, lane = tid & 31, w = tid >> 5;

    const float4* kg = (const float4*)(k_g + head * 8192 + z * 2048);
    const float4* vg = (const float4*)(v_g + head * 8192 + z * 2048);
    for (int i = tid; i < 512; i += 256) {
        float4 kv = kg[i], vv = vg[i];
        if (i & 1) { kB[i >> 1] = kv; vB[i >> 1] = vv; }
        else       { kA[i >> 1] = kv; vA[i >> 1] = vv; }
    }
    __syncthreads();

    #pragma unroll
    for (int il = 0; il < 4; ++il) {
        int l = blockIdx.x * 32 + w * 4 + il;
        const float4* qp = (const float4*)(q_g + head * 8192 + l * 8);
        float4 q0 = qp[0], q1 = qp[1];

        float sum = 0.f;
        float acc[8];
        #pragma unroll
        for (int d = 0; d < 8; d++) acc[d] = 0.f;

        #pragma unroll
        for (int mi = 0; mi < 8; mi++) {
            int m = lane + mi * 32;
            float4 ka = kA[m], kb = kB[m];
            float s = q0.x * ka.x;
            s = fmaf(q0.y, ka.y, s);
            s = fmaf(q0.z, ka.z, s);
            s = fmaf(q0.w, ka.w, s);
            s = fmaf(q1.x, kb.x, s);
            s = fmaf(q1.y, kb.y, s);
            s = fmaf(q1.z, kb.z, s);
            s = fmaf(q1.w, kb.w, s);
            float e = __expf(s);
            sum += e;
            float4 va = vA[m], vb = vB[m];
            acc[0] = fmaf(e, va.x, acc[0]);
            acc[1] = fmaf(e, va.y, acc[1]);
            acc[2] = fmaf(e, va.z, acc[2]);
            acc[3] = fmaf(e, va.w, acc[3]);
            acc[4] = fmaf(e, vb.x, acc[4]);
            acc[5] = fmaf(e, vb.y, acc[5]);
            acc[6] = fmaf(e, vb.z, acc[6]);
            acc[7] = fmaf(e, vb.w, acc[7]);
        }
        #pragma unroll
        for (int o = 16; o > 0; o >>= 1) {
            sum += __shfl_xor_sync(0xffffffffu, sum, o);
            #pragma unroll
            for (int d = 0; d < 8; d++) acc[d] += __shfl_xor_sync(0xffffffffu, acc[d], o);
        }
        if (lane == 0) {
            int base = (l * 4 + head) * 4 + z;
            float4* ap = (float4*)(accp_g + base * 8);
            ap[0] = make_float4(acc[0], acc[1], acc[2], acc[3]);
            ap[1] = make_float4(acc[4], acc[5], acc[6], acc[7]);
            sump_g[base] = sum;
        }
    }
}

// =====================================================================
// Kernel 3: combine attention partials + attn output proj + MLP head.
//           32 blocks x 32 batch each.
// =====================================================================
__global__ void __launch_bounds__(256, 1) mlp_kernel(
    const float* __restrict__ ow, const float* __restrict__ ob,
    const float* __restrict__ d1w, const float* __restrict__ d1b,
    const float* __restrict__ bg1, const float* __restrict__ bb1,
    const float* __restrict__ d2w, const float* __restrict__ d2b,
    const float* __restrict__ bg2, const float* __restrict__ bb2,
    const float* __restrict__ d3w, const float* __restrict__ d3b,
    float* __restrict__ out)
{
    __shared__ float owT[1024], d1T[2048], d2T[2048], d3s[32];
    __shared__ float obs[32], d1bs[64], d2bs[32], s1[64], sb1[64], s2[32], sb2[32];
    __shared__ float att[32 * 32], z1[32 * 32], z2[32 * 64], z3[32 * 32];

    const int tid = threadIdx.x;
    const int bb = blockIdx.x * 32;
    const float bnscale = rsqrtf(1.f + 1e-5f);

    for (int i = tid; i < 1024; i += 256) { int o = i & 31, e = i >> 5; owT[e * 32 + o] = ow[o * 32 + e]; }
    for (int i = tid; i < 2048; i += 256) { int o = i & 63, e = i >> 6; d1T[e * 64 + o] = d1w[o * 32 + e]; }
    for (int i = tid; i < 2048; i += 256) { int o = i & 31, e = i >> 5; d2T[e * 32 + o] = d2w[o * 64 + e]; }
    if (tid < 32) { d3s[tid] = d3w[tid]; obs[tid] = ob[tid]; d2bs[tid] = d2b[tid]; s2[tid] = bg2[tid] * bnscale; sb2[tid] = bb2[tid]; }
    if (tid < 64) { d1bs[tid] = d1b[tid]; s1[tid] = bg1[tid] * bnscale; sb1[tid] = bb1[tid]; }

    // combine attention partials: att[b][e]
    for (int i = tid; i < 1024; i += 256) {
        int b = i >> 5, e = i & 31;
        int head = e >> 3, d = e & 7;
        int base = ((bb + b) * 4 + head) * 4;
        float s = sump_g[base] + sump_g[base + 1] + sump_g[base + 2] + sump_g[base + 3];
        float a = accp_g[base * 8 + d] + accp_g[(base + 1) * 8 + d]
                + accp_g[(base + 2) * 8 + d] + accp_g[(base + 3) * 8 + d];
        att[i] = a / s;
    }
    __syncthreads();

    for (int i = tid; i < 1024; i += 256) {
        int b = i >> 5, o = i & 31;
        float a = obs[o];
        #pragma unroll 8
        for (int e = 0; e < 32; e++) a += att[b * 32 + e] * owT[e * 32 + o];
        z1[b * 32 + o] = a;
    }
    __syncthreads();

    for (int i = tid; i < 2048; i += 256) {
        int b = i >> 6, o = i & 63;
        float a = d1bs[o];
        #pragma unroll 8
        for (int e = 0; e < 32; e++) a += z1[b * 32 + e] * d1T[e * 64 + o];
        a = a * s1[o] + sb1[o];
        z2[b * 64 + o] = fmaxf(a, 0.f);
    }
    __syncthreads();

    for (int i = tid; i < 1024; i += 256) {
        int b = i >> 5, o = i & 31;
        float a = d2bs[o];
        #pragma unroll 8
        for (int e = 0; e < 64; e++) a += z2[b * 64 + e] * d2T[e * 32 + o];
        a = a * s2[o] + sb2[o];
        z3[o * 32 + b] = fmaxf(a, 0.f);
    }
    __syncthreads();

    if (tid < 32) {
        int b = tid;
        float a = d3b[0];
        #pragma unroll 8
        for (int e = 0; e < 32; e++) a += z3[e * 32 + b] * d3s[e];
        out[bb + b] = 1.f / (1.f + __expf(-a));
    }
}

// =====================================================================
extern "C" void kernel_launch(void* const* d_in, const int* in_sizes, int n_in,
                              void* d_out, int out_size)
{
    const float* x      = (const float*)d_in[0];
    const float* emb_w  = (const float*)d_in[1];
    const float* emb_b  = (const float*)d_in[2];
    const float* l1_wih = (const float*)d_in[3];
    const float* l1_whh = (const float*)d_in[4];
    const float* l1_bih = (const float*)d_in[5];
    const float* l1_bhh = (const float*)d_in[6];
    const float* l2_wih = (const float*)d_in[7];
    const float* l2_whh = (const float*)d_in[8];
    const float* l2_bih = (const float*)d_in[9];
    const float* l2_bhh = (const float*)d_in[10];
    const float* attn_w = (const float*)d_in[11];
    const float* attn_b = (const float*)d_in[12];
    const float* attn_ow = (const float*)d_in[13];
    const float* attn_ob = (const float*)d_in[14];
    const float* d1_w   = (const float*)d_in[15];
    const float* d1_b   = (const float*)d_in[16];
    const float* bn1_g  = (const float*)d_in[17];
    const float* bn1_b  = (const float*)d_in[18];
    const float* d2_w   = (const float*)d_in[19];
    const float* d2_b   = (const float*)d_in[20];
    const float* bn2_g  = (const float*)d_in[21];
    const float* bn2_b  = (const float*)d_in[22];
    const float* d3_w   = (const float*)d_in[23];
    const float* d3_b   = (const float*)d_in[24];
    float* out = (float*)d_out;

    const int smem1 = 18624 * 4;   // 74,496 B
    cudaFuncSetAttribute(lstm_kernel, cudaFuncAttributeMaxDynamicSharedMemorySize, smem1);

    lstm_kernel<<<128, 768, smem1>>>(x, emb_w, emb_b,
                                     l1_wih, l1_whh, l1_bih, l1_bhh,
                                     l2_wih, l2_whh, l2_bih, l2_bhh,
                                     attn_w, attn_b);
    attn_kernel<<<dim3(32, 4, 4), 256>>>();
    mlp_kernel<<<32, 256>>>(attn_ow, attn_ob, d1_w, d1_b, bn1_g, bn1_b,
                            d2_w, d2_b, bn2_g, bn2_b, d3_w, d3_b, out);
}

// round 6
// speedup vs baseline: 1.4225x; 1.1290x over previous
#include <cuda_runtime.h>
#include <math.h>

// ---------------- global scratch (no allocations allowed) ----------------
__device__ float q_g[4 * 1024 * 8];
__device__ float k_g[4 * 1024 * 8];
__device__ float v_g[4 * 1024 * 8];

typedef unsigned long long u64;

__device__ __forceinline__ float tanh_f(float x) {
    float y; asm("tanh.approx.f32 %0, %1;" : "=f"(y) : "f"(x)); return y;
}
__device__ __forceinline__ float sigf(float x) {
    return fmaf(0.5f, tanh_f(0.5f * x), 0.5f);
}
__device__ __forceinline__ u64 pack2(float a, float b) {
    u64 r; asm("mov.b64 %0, {%1,%2};" : "=l"(r) : "f"(a), "f"(b)); return r;
}
__device__ __forceinline__ void unpack2(u64 v, float& a, float& b) {
    asm("mov.b64 {%0,%1}, %2;" : "=f"(a), "=f"(b) : "l"(v));
}
__device__ __forceinline__ u64 fma2(u64 a, u64 b, u64 c) {
    u64 d; asm("fma.rn.f32x2 %0, %1, %2, %3;" : "=l"(d) : "l"(a), "l"(b), "l"(c)); return d;
}

// =====================================================================
// Kernel 1: pipelined LSTM1 + LSTM2, balanced 16-iter GEMVs.
//   threads 0-511  : LSTM1 — gate pair p=tid&127 (gates 2p,2p+1),
//                    k-quarter q=tid>>7 (16 rows each, 16 iters)
//   threads 512-895: LSTM2 — gate pair p=t2&63, k-split s=t2>>6 (6 splits
//                    of 16 rows of concat(h1[64],h2[32]), 16 iters)
//   128 CTAs x 896 threads, 8 batch rows per CTA.
// =====================================================================
__global__ void __launch_bounds__(896, 1) lstm_kernel(
    const float* __restrict__ x,
    const float* __restrict__ emb_w, const float* __restrict__ emb_b,
    const float* __restrict__ w1, const float* __restrict__ u1,
    const float* __restrict__ b1i, const float* __restrict__ b1h,
    const float* __restrict__ w2, const float* __restrict__ u2,
    const float* __restrict__ b2i, const float* __restrict__ b2h,
    const float* __restrict__ attn_w, const float* __restrict__ attn_b)
{
    extern __shared__ __align__(16) float sm[];
    float* g1p    = sm;              // [4][8][256]  8192
    float* g2p    = g1p + 8192;     // [6][8][128]  6144
    float* pt1s   = g2p + 6144;     // [16][256]    4096
    float* pe     = pt1s + 4096;    // [16][32]      512
    float* xs     = pe + 512;       // [16][8]       128
    float* hcat   = xs + 128;       // [2][96][8]   1536
    float* embw_s = hcat + 1536;    // 32
    float* embb_s = embw_s + 32;    // 32

    const int tid = threadIdx.x;
    const int b0 = blockIdx.x * 8;

    // ---- shared prologue ----
    if (tid < 512) {
        int t = tid >> 5, e = tid & 31;
        int half = e >> 1;
        float div = __expf(-(float)(2 * half) * (9.210340371976184f / 32.0f));
        float arg = (float)t * div;
        pe[tid] = (e & 1) ? cosf(arg) : sinf(arg);
    }
    if (tid < 32) { embw_s[tid] = emb_w[tid]; embb_s[tid] = emb_b[tid]; }
    if (tid < 128) { int t = tid >> 3, b = tid & 7; xs[tid] = x[(b0 + b) * 16 + t]; }
    for (int i = tid; i < 1536; i += 896) hcat[i] = 0.f;
    __syncthreads();

    // ---- pt1s + we1 (embedding folded into LSTM1): threads < 256 ----
    if (tid < 256) {
        int gate = 2 * (tid & 127) + (tid >> 7);
        float w1r[32];
        const float4* w1p = (const float4*)(w1 + gate * 32);
        #pragma unroll
        for (int qq = 0; qq < 8; qq++) {
            float4 v = w1p[qq];
            w1r[qq*4+0]=v.x; w1r[qq*4+1]=v.y; w1r[qq*4+2]=v.z; w1r[qq*4+3]=v.w;
        }
        float we1 = 0.f, wb = b1i[gate] + b1h[gate];
        #pragma unroll
        for (int e = 0; e < 32; e++) {
            we1 = fmaf(w1r[e], embw_s[e], we1);
            wb  = fmaf(w1r[e], embb_s[e], wb);
        }
        g1p[gate] = we1;   // stash
        #pragma unroll
        for (int t = 0; t < 16; t++) {
            float s = wb;
            #pragma unroll
            for (int e = 0; e < 32; e++) s = fmaf(w1r[e], pe[t * 32 + e], s);
            pt1s[t * 256 + gate] = s;
        }
    }
    __syncthreads();

    // ---- per-thread register setup ----
    float wreg[32];
    u64 weA = 0, weB = 0, bvA = 0, bvB = 0;
    float c1r = 0.f, c2r = 0.f;
    int pA = 0, qA = 0, pB = 0, sB = 0;

    if (tid < 512) {
        pA = tid & 127; qA = tid >> 7;
        const float4* a0 = (const float4*)(u1 + (2 * pA) * 64 + qA * 16);
        const float4* a1 = (const float4*)(u1 + (2 * pA + 1) * 64 + qA * 16);
        #pragma unroll
        for (int qq = 0; qq < 4; qq++) {
            float4 v = a0[qq];
            wreg[qq*4+0]=v.x; wreg[qq*4+1]=v.y; wreg[qq*4+2]=v.z; wreg[qq*4+3]=v.w;
            float4 u = a1[qq];
            wreg[16+qq*4+0]=u.x; wreg[16+qq*4+1]=u.y; wreg[16+qq*4+2]=u.z; wreg[16+qq*4+3]=u.w;
        }
        if (qA == 0) {
            float wa = g1p[2 * pA], wbv = g1p[2 * pA + 1];
            weA = pack2(wa, wa); weB = pack2(wbv, wbv);
        }
    } else {
        int t2 = tid - 512;
        pB = t2 & 63; sB = t2 >> 6;   // sB in [0,6)
        #pragma unroll
        for (int g = 0; g < 2; g++) {
            int row = 2 * pB + g;
            const float4* p = (sB < 4)
                ? (const float4*)(w2 + row * 64 + sB * 16)
                : (const float4*)(u2 + row * 32 + (sB - 4) * 16);
            #pragma unroll
            for (int qq = 0; qq < 4; qq++) {
                float4 v = p[qq];
                wreg[g*16+qq*4+0]=v.x; wreg[g*16+qq*4+1]=v.y;
                wreg[g*16+qq*4+2]=v.z; wreg[g*16+qq*4+3]=v.w;
            }
        }
        if (sB == 0) {
            float ba = b2i[2 * pB] + b2h[2 * pB];
            float bb = b2i[2 * pB + 1] + b2h[2 * pB + 1];
            bvA = pack2(ba, ba); bvB = pack2(bb, bb);
        }
    }
    __syncthreads();   // stash in g1p consumed before main loop overwrites

    // ---- pipelined main loop: 17 iterations ----
    for (int i = 0; i < 17; ++i) {
        int cur = i & 1;
        const float* hc = hcat + cur * 768;
        float* hn = hcat + (cur ^ 1) * 768;
        if (tid < 512) {
            if (i < 16) {
                u64 a00, a01, a02, a03, a10, a11, a12, a13;
                if (qA == 0) {
                    float pt0 = pt1s[i * 256 + 2 * pA];
                    float pt1 = pt1s[i * 256 + 2 * pA + 1];
                    u64 p0 = pack2(pt0, pt0), p1 = pack2(pt1, pt1);
                    const ulonglong2* xp = (const ulonglong2*)&xs[i * 8];
                    ulonglong2 x01 = xp[0], x23 = xp[1];
                    a00 = fma2(weA, x01.x, p0); a01 = fma2(weA, x01.y, p0);
                    a02 = fma2(weA, x23.x, p0); a03 = fma2(weA, x23.y, p0);
                    a10 = fma2(weB, x01.x, p1); a11 = fma2(weB, x01.y, p1);
                    a12 = fma2(weB, x23.x, p1); a13 = fma2(weB, x23.y, p1);
                } else {
                    a00=a01=a02=a03=a10=a11=a12=a13=0ULL;
                }
                const float* hk = hc + qA * 128;
                #pragma unroll
                for (int k = 0; k < 16; k++) {
                    ulonglong2 hA = *(const ulonglong2*)&hk[k * 8];
                    ulonglong2 hB = *(const ulonglong2*)&hk[k * 8 + 4];
                    u64 w0 = pack2(wreg[k], wreg[k]);
                    a00 = fma2(w0, hA.x, a00); a01 = fma2(w0, hA.y, a01);
                    a02 = fma2(w0, hB.x, a02); a03 = fma2(w0, hB.y, a03);
                    u64 w1p = pack2(wreg[16 + k], wreg[16 + k]);
                    a10 = fma2(w1p, hA.x, a10); a11 = fma2(w1p, hA.y, a11);
                    a12 = fma2(w1p, hB.x, a12); a13 = fma2(w1p, hB.y, a13);
                }
                float f0, f1;
                float* gp0 = g1p + qA * 2048 + 2 * pA;
                unpack2(a00, f0, f1); gp0[0]    = f0; gp0[256]  = f1;
                unpack2(a01, f0, f1); gp0[512]  = f0; gp0[768]  = f1;
                unpack2(a02, f0, f1); gp0[1024] = f0; gp0[1280] = f1;
                unpack2(a03, f0, f1); gp0[1536] = f0; gp0[1792] = f1;
                float* gp1 = gp0 + 1;
                unpack2(a10, f0, f1); gp1[0]    = f0; gp1[256]  = f1;
                unpack2(a11, f0, f1); gp1[512]  = f0; gp1[768]  = f1;
                unpack2(a12, f0, f1); gp1[1024] = f0; gp1[1280] = f1;
                unpack2(a13, f0, f1); gp1[1536] = f0; gp1[1792] = f1;

                asm volatile("bar.sync 1, 512;" ::: "memory");

                // cell update: one cell per thread, sum 4 quarters
                int b = tid >> 6, j = tid & 63;
                const float* gp = g1p + b * 256 + j;
                float gi = gp[0]       + gp[2048]      + gp[4096]      + gp[6144];
                float gf = gp[64]      + gp[2048+64]   + gp[4096+64]   + gp[6144+64];
                float gg = gp[128]     + gp[2048+128]  + gp[4096+128]  + gp[6144+128];
                float go = gp[192]     + gp[2048+192]  + gp[4096+192]  + gp[6144+192];
                float nc = sigf(gf) * c1r + sigf(gi) * tanh_f(gg);
                c1r = nc;
                hn[j * 8 + b] = sigf(go) * tanh_f(nc);
            }
        } else {
            if (i >= 1) {
                int t2 = tid - 512;
                u64 a00, a01, a02, a03, a10, a11, a12, a13;
                if (sB == 0) { a00=a01=a02=a03=bvA; a10=a11=a12=a13=bvB; }
                else { a00=a01=a02=a03=a10=a11=a12=a13=0ULL; }
                const float* hk = hc + sB * 128;   // 16 rows per split
                #pragma unroll
                for (int c = 0; c < 16; c++) {
                    ulonglong2 hA = *(const ulonglong2*)&hk[c * 8];
                    ulonglong2 hB = *(const ulonglong2*)&hk[c * 8 + 4];
                    u64 w0 = pack2(wreg[c], wreg[c]);
                    a00 = fma2(w0, hA.x, a00); a01 = fma2(w0, hA.y, a01);
                    a02 = fma2(w0, hB.x, a02); a03 = fma2(w0, hB.y, a03);
                    u64 w1p = pack2(wreg[16 + c], wreg[16 + c]);
                    a10 = fma2(w1p, hA.x, a10); a11 = fma2(w1p, hA.y, a11);
                    a12 = fma2(w1p, hB.x, a12); a13 = fma2(w1p, hB.y, a13);
                }
                float f0, f1;
                float* gp0 = g2p + sB * 1024 + 2 * pB;
                unpack2(a00, f0, f1); gp0[0]   = f0; gp0[128] = f1;
                unpack2(a01, f0, f1); gp0[256] = f0; gp0[384] = f1;
                unpack2(a02, f0, f1); gp0[512] = f0; gp0[640] = f1;
                unpack2(a03, f0, f1); gp0[768] = f0; gp0[896] = f1;
                float* gp1 = gp0 + 1;
                unpack2(a10, f0, f1); gp1[0]   = f0; gp1[128] = f1;
                unpack2(a11, f0, f1); gp1[256] = f0; gp1[384] = f1;
                unpack2(a12, f0, f1); gp1[512] = f0; gp1[640] = f1;
                unpack2(a13, f0, f1); gp1[768] = f0; gp1[896] = f1;

                asm volatile("bar.sync 2, 384;" ::: "memory");

                // cell update: one cell per thread (first 256), sum 6 splits
                if (t2 < 256) {
                    int b = t2 >> 5, j = t2 & 31;
                    const float* gp = g2p + b * 128 + j;
                    float gi = 0.f, gf = 0.f, gg = 0.f, go = 0.f;
                    #pragma unroll
                    for (int s = 0; s < 6; s++) {
                        gi += gp[s * 1024];
                        gf += gp[s * 1024 + 32];
                        gg += gp[s * 1024 + 64];
                        go += gp[s * 1024 + 96];
                    }
                    float nc = sigf(gf) * c2r + sigf(gi) * tanh_f(gg);
                    c2r = nc;
                    hn[(64 + j) * 8 + b] = sigf(go) * tanh_f(nc);
                }
            }
        }
        __syncthreads();
    }

    // ---- qkv projection of l2_final = h2(15) + h1(15)[:32] ----
    // h1(15) in hcat buffer 0 rows 0-63; h2(15) in hcat buffer 1 rows 64-95.
    if (tid < 768) {
        int b = tid / 96, g = tid % 96;
        float acc = attn_b[g];
        #pragma unroll 8
        for (int e = 0; e < 32; e++) {
            float vv = hcat[e * 8 + b] + hcat[768 + (64 + e) * 8 + b];
            acc = fmaf(vv, attn_w[g * 32 + e], acc);
        }
        int m = b0 + b;
        int head = (g & 31) >> 3;
        int d = g & 7;
        if (g < 32)      q_g[head * 8192 + m * 8 + d] = acc * 0.3535533905932738f;
        else if (g < 64) k_g[head * 8192 + m * 8 + d] = acc;
        else             v_g[head * 8192 + m * 8 + d] = acc;
    }
}

// =====================================================================
// Kernel 2: fused attention + MLP head. 128 CTAs x 256 thr, 8 rows each.
//   Two passes of 2 heads: stage k/v SoA float4 in smem, full softmax*V,
//   then dense head for the CTA's 8 rows, write out directly.
// =====================================================================
__global__ void __launch_bounds__(256, 1) attn_mlp_kernel(
    const float* __restrict__ ow, const float* __restrict__ ob,
    const float* __restrict__ d1w, const float* __restrict__ d1b,
    const float* __restrict__ bg1, const float* __restrict__ bb1,
    const float* __restrict__ d2w, const float* __restrict__ d2b,
    const float* __restrict__ bg2, const float* __restrict__ bb2,
    const float* __restrict__ d3w, const float* __restrict__ d3b,
    float* __restrict__ out)
{
    extern __shared__ __align__(16) float smf[];
    float4* kS = (float4*)smf;             // [2 heads][2 parts][1024] = 4096 f4
    float4* vS = kS + 4096;                // 4096 f4
    float* fb   = (float*)(vS + 4096);
    float* owT  = fb;                      // [32][32] 1024
    float* d1T  = owT + 1024;              // [32][64] 2048
    float* d2T  = d1T + 2048;              // [64][32] 2048
    float* d3s  = d2T + 2048;              // 32
    float* obs  = d3s + 32;                // 32
    float* d1bs = obs + 32;                // 64
    float* s1v  = d1bs + 64;               // 64
    float* sb1  = s1v + 64;                // 64
    float* d2bs = sb1 + 64;                // 32
    float* s2v  = d2bs + 32;               // 32
    float* sb2  = s2v + 32;                // 32
    float* att  = sb2 + 32;                // [8][32] 256
    float* z1   = att + 256;               // [8][32] 256
    float* z2   = z1 + 256;                // [8][64] 512
    float* z3   = z2 + 512;                // [32][8] 256

    const int tid = threadIdx.x;
    const int lane = tid & 31, w = tid >> 5;
    const int r0 = blockIdx.x * 8;
    const float bnscale = rsqrtf(1.f + 1e-5f);

    // ---- stage MLP weights once ----
    for (int i = tid; i < 1024; i += 256) { int o = i & 31, e = i >> 5; owT[e * 32 + o] = ow[o * 32 + e]; }
    for (int i = tid; i < 2048; i += 256) { int o = i & 63, e = i >> 6; d1T[e * 64 + o] = d1w[o * 32 + e]; }
    for (int i = tid; i < 2048; i += 256) { int o = i & 31, e = i >> 5; d2T[e * 32 + o] = d2w[o * 64 + e]; }
    if (tid < 32) { d3s[tid] = d3w[tid]; obs[tid] = ob[tid]; d2bs[tid] = d2b[tid]; s2v[tid] = bg2[tid] * bnscale; sb2[tid] = bb2[tid]; }
    if (tid < 64) { d1bs[tid] = d1b[tid]; s1v[tid] = bg1[tid] * bnscale; sb1[tid] = bb1[tid]; }

    // ---- attention: 2 passes of 2 heads ----
    for (int p = 0; p < 2; ++p) {
        __syncthreads();   // protect kS/vS from previous pass readers
        for (int i = tid; i < 4096; i += 256) {
            int h2 = i >> 11, rem = i & 2047;
            int m = rem >> 1, part = rem & 1;
            const float4* kg = (const float4*)(k_g + (2 * p + h2) * 8192);
            const float4* vg = (const float4*)(v_g + (2 * p + h2) * 8192);
            kS[h2 * 2048 + part * 1024 + m] = kg[rem];
            vS[h2 * 2048 + part * 1024 + m] = vg[rem];
        }
        __syncthreads();

        // 16 (row, head2) pairs; warp w handles pairs w and w+8
        #pragma unroll
        for (int pp = 0; pp < 2; ++pp) {
            int pair = w + pp * 8;
            int row = pair & 7, h2 = pair >> 3;
            int head = 2 * p + h2;
            const float4* qp = (const float4*)(q_g + head * 8192 + (r0 + row) * 8);
            float4 q0 = qp[0], q1 = qp[1];
            const float4* kA = kS + h2 * 2048;
            const float4* kB = kA + 1024;
            const float4* vA = vS + h2 * 2048;
            const float4* vB = vA + 1024;

            float sum = 0.f;
            float acc[8];
            #pragma unroll
            for (int d = 0; d < 8; d++) acc[d] = 0.f;

            #pragma unroll 4
            for (int mi = 0; mi < 32; mi++) {
                int m = lane + mi * 32;
                float4 ka = kA[m], kb = kB[m];
                float s = q0.x * ka.x;
                s = fmaf(q0.y, ka.y, s);
                s = fmaf(q0.z, ka.z, s);
                s = fmaf(q0.w, ka.w, s);
                s = fmaf(q1.x, kb.x, s);
                s = fmaf(q1.y, kb.y, s);
                s = fmaf(q1.z, kb.z, s);
                s = fmaf(q1.w, kb.w, s);
                float e = __expf(s);
                sum += e;
                float4 va = vA[m], vb = vB[m];
                acc[0] = fmaf(e, va.x, acc[0]);
                acc[1] = fmaf(e, va.y, acc[1]);
                acc[2] = fmaf(e, va.z, acc[2]);
                acc[3] = fmaf(e, va.w, acc[3]);
                acc[4] = fmaf(e, vb.x, acc[4]);
                acc[5] = fmaf(e, vb.y, acc[5]);
                acc[6] = fmaf(e, vb.z, acc[6]);
                acc[7] = fmaf(e, vb.w, acc[7]);
            }
            #pragma unroll
            for (int o = 16; o > 0; o >>= 1) {
                sum += __shfl_xor_sync(0xffffffffu, sum, o);
                #pragma unroll
                for (int d = 0; d < 8; d++) acc[d] += __shfl_xor_sync(0xffffffffu, acc[d], o);
            }
            if (lane == 0) {
                float inv = 1.f / sum;
                #pragma unroll
                for (int d = 0; d < 8; d++) att[row * 32 + head * 8 + d] = acc[d] * inv;
            }
        }
    }
    __syncthreads();

    // ---- attention output projection: 8x32 = 256 outputs ----
    {
        int b = tid >> 5, o = tid & 31;
        float a = obs[o];
        #pragma unroll 8
        for (int e = 0; e < 32; e++) a += att[b * 32 + e] * owT[e * 32 + o];
        z1[b * 32 + o] = a;
    }
    __syncthreads();

    // ---- dense1 + bn1 + relu: 8x64 = 512 outputs ----
    for (int i = tid; i < 512; i += 256) {
        int b = i >> 6, o = i & 63;
        float a = d1bs[o];
        #pragma unroll 8
        for (int e = 0; e < 32; e++) a += z1[b * 32 + e] * d1T[e * 64 + o];
        a = a * s1v[o] + sb1[o];
        z2[b * 64 + o] = fmaxf(a, 0.f);
    }
    __syncthreads();

    // ---- dense2 + bn2 + relu: 8x32 (store transposed [o][b]) ----
    {
        int b = tid >> 5, o = tid & 31;
        float a = d2bs[o];
        #pragma unroll 8
        for (int e = 0; e < 64; e++) a += z2[b * 64 + e] * d2T[e * 32 + o];
        a = a * s2v[o] + sb2[o];
        z3[o * 8 + b] = fmaxf(a, 0.f);
    }
    __syncthreads();

    // ---- dense3 + sigmoid ----
    if (tid < 8) {
        int b = tid;
        float a = d3b[0];
        #pragma unroll 8
        for (int e = 0; e < 32; e++) a += z3[e * 8 + b] * d3s[e];
        out[r0 + b] = 1.f / (1.f + __expf(-a));
    }
}

// =====================================================================
extern "C" void kernel_launch(void* const* d_in, const int* in_sizes, int n_in,
                              void* d_out, int out_size)
{
    const float* x      = (const float*)d_in[0];
    const float* emb_w  = (const float*)d_in[1];
    const float* emb_b  = (const float*)d_in[2];
    const float* l1_wih = (const float*)d_in[3];
    const float* l1_whh = (const float*)d_in[4];
    const float* l1_bih = (const float*)d_in[5];
    const float* l1_bhh = (const float*)d_in[6];
    const float* l2_wih = (const float*)d_in[7];
    const float* l2_whh = (const float*)d_in[8];
    const float* l2_bih = (const float*)d_in[9];
    const float* l2_bhh = (const float*)d_in[10];
    const float* attn_w = (const float*)d_in[11];
    const float* attn_b = (const float*)d_in[12];
    const float* attn_ow = (const float*)d_in[13];
    const float* attn_ob = (const float*)d_in[14];
    const float* d1_w   = (const float*)d_in[15];
    const float* d1_b   = (const float*)d_in[16];
    const float* bn1_g  = (const float*)d_in[17];
    const float* bn1_b  = (const float*)d_in[18];
    const float* d2_w   = (const float*)d_in[19];
    const float* d2_b   = (const float*)d_in[20];
    const float* bn2_g  = (const float*)d_in[21];
    const float* bn2_b  = (const float*)d_in[22];
    const float* d3_w   = (const float*)d_in[23];
    const float* d3_b   = (const float*)d_in[24];
    float* out = (float*)d_out;

    const int smem1 = 20672 * 4;                     // 82,688 B
    const int smem2 = (4096 + 4096) * 16 + 6800 * 4; // 158,272 B
    cudaFuncSetAttribute(lstm_kernel, cudaFuncAttributeMaxDynamicSharedMemorySize, smem1);
    cudaFuncSetAttribute(attn_mlp_kernel, cudaFuncAttributeMaxDynamicSharedMemorySize, smem2);

    lstm_kernel<<<128, 896, smem1>>>(x, emb_w, emb_b,
                                     l1_wih, l1_whh, l1_bih, l1_bhh,
                                     l2_wih, l2_whh, l2_bih, l2_bhh,
                                     attn_w, attn_b);
    attn_mlp_kernel<<<128, 256, smem2>>>(attn_ow, attn_ob, d1_w, d1_b,
                                         bn1_g, bn1_b, d2_w, d2_b,
                                         bn2_g, bn2_b, d3_w, d3_b, out);
}

// round 7
// speedup vs baseline: 1.5621x; 1.0981x over previous
#include <cuda_runtime.h>
#include <math.h>

// ---------------- global scratch (no allocations allowed) ----------------
__device__ float q_g[4 * 1024 * 8];
__device__ float k_g[4 * 1024 * 8];
__device__ float v_g[4 * 1024 * 8];

typedef unsigned long long u64;

__device__ __forceinline__ float tanh_f(float x) {
    float y; asm("tanh.approx.f32 %0, %1;" : "=f"(y) : "f"(x)); return y;
}
__device__ __forceinline__ float sigf(float x) {
    return fmaf(0.5f, tanh_f(0.5f * x), 0.5f);
}
__device__ __forceinline__ u64 pack2(float a, float b) {
    u64 r; asm("mov.b64 %0, {%1,%2};" : "=l"(r) : "f"(a), "f"(b)); return r;
}
__device__ __forceinline__ void unpack2(u64 v, float& a, float& b) {
    asm("mov.b64 {%0,%1}, %2;" : "=f"(a), "=f"(b) : "l"(v));
}
__device__ __forceinline__ u64 fma2(u64 a, u64 b, u64 c) {
    u64 d; asm("fma.rn.f32x2 %0, %1, %2, %3;" : "=l"(d) : "l"(a), "l"(b), "l"(c)); return d;
}

// =====================================================================
// Kernel 1: pipelined LSTM1 + LSTM2, balanced 16-iter GEMVs.
//   threads 0-511  : LSTM1 — gate pair p=tid&127 (gates 2p,2p+1),
//                    k-quarter q=tid>>7 (16 rows each, 16 iters)
//   threads 512-895: LSTM2 — gate pair p=t2&63, k-split s=t2>>6 (6 splits
//                    of 16 rows of concat(h1[64],h2[32]), 16 iters)
//   128 CTAs x 896 threads, 8 batch rows per CTA.
// =====================================================================
__global__ void __launch_bounds__(896, 1) lstm_kernel(
    const float* __restrict__ x,
    const float* __restrict__ emb_w, const float* __restrict__ emb_b,
    const float* __restrict__ w1, const float* __restrict__ u1,
    const float* __restrict__ b1i, const float* __restrict__ b1h,
    const float* __restrict__ w2, const float* __restrict__ u2,
    const float* __restrict__ b2i, const float* __restrict__ b2h,
    const float* __restrict__ attn_w, const float* __restrict__ attn_b)
{
    extern __shared__ __align__(16) float sm[];
    float* g1p    = sm;              // [4][8][256]  8192
    float* g2p    = g1p + 8192;     // [6][8][128]  6144
    float* pt1s   = g2p + 6144;     // [16][256]    4096
    float* pe     = pt1s + 4096;    // [16][32]      512
    float* xs     = pe + 512;       // [16][8]       128
    float* hcat   = xs + 128;       // [2][96][8]   1536
    float* embw_s = hcat + 1536;    // 32
    float* embb_s = embw_s + 32;    // 32

    const int tid = threadIdx.x;
    const int b0 = blockIdx.x * 8;

    // ---- shared prologue ----
    if (tid < 512) {
        int t = tid >> 5, e = tid & 31;
        int half = e >> 1;
        float div = __expf(-(float)(2 * half) * (9.210340371976184f / 32.0f));
        float arg = (float)t * div;
        pe[tid] = (e & 1) ? cosf(arg) : sinf(arg);
    }
    if (tid < 32) { embw_s[tid] = emb_w[tid]; embb_s[tid] = emb_b[tid]; }
    if (tid < 128) { int t = tid >> 3, b = tid & 7; xs[tid] = x[(b0 + b) * 16 + t]; }
    for (int i = tid; i < 1536; i += 896) hcat[i] = 0.f;
    __syncthreads();

    // ---- pt1s + we1 (embedding folded into LSTM1): threads < 256 ----
    if (tid < 256) {
        int gate = 2 * (tid & 127) + (tid >> 7);
        float w1r[32];
        const float4* w1p = (const float4*)(w1 + gate * 32);
        #pragma unroll
        for (int qq = 0; qq < 8; qq++) {
            float4 v = w1p[qq];
            w1r[qq*4+0]=v.x; w1r[qq*4+1]=v.y; w1r[qq*4+2]=v.z; w1r[qq*4+3]=v.w;
        }
        float we1 = 0.f, wb = b1i[gate] + b1h[gate];
        #pragma unroll
        for (int e = 0; e < 32; e++) {
            we1 = fmaf(w1r[e], embw_s[e], we1);
            wb  = fmaf(w1r[e], embb_s[e], wb);
        }
        g1p[gate] = we1;   // stash
        #pragma unroll
        for (int t = 0; t < 16; t++) {
            float s = wb;
            #pragma unroll
            for (int e = 0; e < 32; e++) s = fmaf(w1r[e], pe[t * 32 + e], s);
            pt1s[t * 256 + gate] = s;
        }
    }
    __syncthreads();

    // ---- per-thread register setup ----
    float wreg[32];
    u64 weA = 0, weB = 0, bvA = 0, bvB = 0;
    float c1r = 0.f, c2r = 0.f;
    int pA = 0, qA = 0, pB = 0, sB = 0;

    if (tid < 512) {
        pA = tid & 127; qA = tid >> 7;
        const float4* a0 = (const float4*)(u1 + (2 * pA) * 64 + qA * 16);
        const float4* a1 = (const float4*)(u1 + (2 * pA + 1) * 64 + qA * 16);
        #pragma unroll
        for (int qq = 0; qq < 4; qq++) {
            float4 v = a0[qq];
            wreg[qq*4+0]=v.x; wreg[qq*4+1]=v.y; wreg[qq*4+2]=v.z; wreg[qq*4+3]=v.w;
            float4 u = a1[qq];
            wreg[16+qq*4+0]=u.x; wreg[16+qq*4+1]=u.y; wreg[16+qq*4+2]=u.z; wreg[16+qq*4+3]=u.w;
        }
        if (qA == 0) {
            float wa = g1p[2 * pA], wbv = g1p[2 * pA + 1];
            weA = pack2(wa, wa); weB = pack2(wbv, wbv);
        }
    } else {
        int t2 = tid - 512;
        pB = t2 & 63; sB = t2 >> 6;   // sB in [0,6)
        #pragma unroll
        for (int g = 0; g < 2; g++) {
            int row = 2 * pB + g;
            const float4* p = (sB < 4)
                ? (const float4*)(w2 + row * 64 + sB * 16)
                : (const float4*)(u2 + row * 32 + (sB - 4) * 16);
            #pragma unroll
            for (int qq = 0; qq < 4; qq++) {
                float4 v = p[qq];
                wreg[g*16+qq*4+0]=v.x; wreg[g*16+qq*4+1]=v.y;
                wreg[g*16+qq*4+2]=v.z; wreg[g*16+qq*4+3]=v.w;
            }
        }
        if (sB == 0) {
            float ba = b2i[2 * pB] + b2h[2 * pB];
            float bb = b2i[2 * pB + 1] + b2h[2 * pB + 1];
            bvA = pack2(ba, ba); bvB = pack2(bb, bb);
        }
    }
    __syncthreads();   // stash in g1p consumed before main loop overwrites

    // ---- pipelined main loop: 17 iterations ----
    for (int i = 0; i < 17; ++i) {
        int cur = i & 1;
        const float* hc = hcat + cur * 768;
        float* hn = hcat + (cur ^ 1) * 768;
        if (tid < 512) {
            if (i < 16) {
                u64 a00, a01, a02, a03, a10, a11, a12, a13;
                if (qA == 0) {
                    float pt0 = pt1s[i * 256 + 2 * pA];
                    float pt1 = pt1s[i * 256 + 2 * pA + 1];
                    u64 p0 = pack2(pt0, pt0), p1 = pack2(pt1, pt1);
                    const ulonglong2* xp = (const ulonglong2*)&xs[i * 8];
                    ulonglong2 x01 = xp[0], x23 = xp[1];
                    a00 = fma2(weA, x01.x, p0); a01 = fma2(weA, x01.y, p0);
                    a02 = fma2(weA, x23.x, p0); a03 = fma2(weA, x23.y, p0);
                    a10 = fma2(weB, x01.x, p1); a11 = fma2(weB, x01.y, p1);
                    a12 = fma2(weB, x23.x, p1); a13 = fma2(weB, x23.y, p1);
                } else {
                    a00=a01=a02=a03=a10=a11=a12=a13=0ULL;
                }
                const float* hk = hc + qA * 128;
                #pragma unroll
                for (int k = 0; k < 16; k++) {
                    ulonglong2 hA = *(const ulonglong2*)&hk[k * 8];
                    ulonglong2 hB = *(const ulonglong2*)&hk[k * 8 + 4];
                    u64 w0 = pack2(wreg[k], wreg[k]);
                    a00 = fma2(w0, hA.x, a00); a01 = fma2(w0, hA.y, a01);
                    a02 = fma2(w0, hB.x, a02); a03 = fma2(w0, hB.y, a03);
                    u64 w1p = pack2(wreg[16 + k], wreg[16 + k]);
                    a10 = fma2(w1p, hA.x, a10); a11 = fma2(w1p, hA.y, a11);
                    a12 = fma2(w1p, hB.x, a12); a13 = fma2(w1p, hB.y, a13);
                }
                float f0, f1;
                float* gp0 = g1p + qA * 2048 + 2 * pA;
                unpack2(a00, f0, f1); gp0[0]    = f0; gp0[256]  = f1;
                unpack2(a01, f0, f1); gp0[512]  = f0; gp0[768]  = f1;
                unpack2(a02, f0, f1); gp0[1024] = f0; gp0[1280] = f1;
                unpack2(a03, f0, f1); gp0[1536] = f0; gp0[1792] = f1;
                float* gp1 = gp0 + 1;
                unpack2(a10, f0, f1); gp1[0]    = f0; gp1[256]  = f1;
                unpack2(a11, f0, f1); gp1[512]  = f0; gp1[768]  = f1;
                unpack2(a12, f0, f1); gp1[1024] = f0; gp1[1280] = f1;
                unpack2(a13, f0, f1); gp1[1536] = f0; gp1[1792] = f1;

                asm volatile("bar.sync 1, 512;" ::: "memory");

                // cell update: one cell per thread, sum 4 quarters
                int b = tid >> 6, j = tid & 63;
                const float* gp = g1p + b * 256 + j;
                float gi = gp[0]       + gp[2048]      + gp[4096]      + gp[6144];
                float gf = gp[64]      + gp[2048+64]   + gp[4096+64]   + gp[6144+64];
                float gg = gp[128]     + gp[2048+128]  + gp[4096+128]  + gp[6144+128];
                float go = gp[192]     + gp[2048+192]  + gp[4096+192]  + gp[6144+192];
                float nc = sigf(gf) * c1r + sigf(gi) * tanh_f(gg);
                c1r = nc;
                hn[j * 8 + b] = sigf(go) * tanh_f(nc);
            }
        } else {
            if (i >= 1) {
                int t2 = tid - 512;
                u64 a00, a01, a02, a03, a10, a11, a12, a13;
                if (sB == 0) { a00=a01=a02=a03=bvA; a10=a11=a12=a13=bvB; }
                else { a00=a01=a02=a03=a10=a11=a12=a13=0ULL; }
                const float* hk = hc + sB * 128;   // 16 rows per split
                #pragma unroll
                for (int c = 0; c < 16; c++) {
                    ulonglong2 hA = *(const ulonglong2*)&hk[c * 8];
                    ulonglong2 hB = *(const ulonglong2*)&hk[c * 8 + 4];
                    u64 w0 = pack2(wreg[c], wreg[c]);
                    a00 = fma2(w0, hA.x, a00); a01 = fma2(w0, hA.y, a01);
                    a02 = fma2(w0, hB.x, a02); a03 = fma2(w0, hB.y, a03);
                    u64 w1p = pack2(wreg[16 + c], wreg[16 + c]);
                    a10 = fma2(w1p, hA.x, a10); a11 = fma2(w1p, hA.y, a11);
                    a12 = fma2(w1p, hB.x, a12); a13 = fma2(w1p, hB.y, a13);
                }
                float f0, f1;
                float* gp0 = g2p + sB * 1024 + 2 * pB;
                unpack2(a00, f0, f1); gp0[0]   = f0; gp0[128] = f1;
                unpack2(a01, f0, f1); gp0[256] = f0; gp0[384] = f1;
                unpack2(a02, f0, f1); gp0[512] = f0; gp0[640] = f1;
                unpack2(a03, f0, f1); gp0[768] = f0; gp0[896] = f1;
                float* gp1 = gp0 + 1;
                unpack2(a10, f0, f1); gp1[0]   = f0; gp1[128] = f1;
                unpack2(a11, f0, f1); gp1[256] = f0; gp1[384] = f1;
                unpack2(a12, f0, f1); gp1[512] = f0; gp1[640] = f1;
                unpack2(a13, f0, f1); gp1[768] = f0; gp1[896] = f1;

                asm volatile("bar.sync 2, 384;" ::: "memory");

                // cell update: one cell per thread (first 256), sum 6 splits
                if (t2 < 256) {
                    int b = t2 >> 5, j = t2 & 31;
                    const float* gp = g2p + b * 128 + j;
                    float gi = 0.f, gf = 0.f, gg = 0.f, go = 0.f;
                    #pragma unroll
                    for (int s = 0; s < 6; s++) {
                        gi += gp[s * 1024];
                        gf += gp[s * 1024 + 32];
                        gg += gp[s * 1024 + 64];
                        go += gp[s * 1024 + 96];
                    }
                    float nc = sigf(gf) * c2r + sigf(gi) * tanh_f(gg);
                    c2r = nc;
                    hn[(64 + j) * 8 + b] = sigf(go) * tanh_f(nc);
                }
            }
        }
        __syncthreads();
    }

    // ---- qkv projection of l2_final = h2(15) + h1(15)[:32] ----
    if (tid < 768) {
        int b = tid / 96, g = tid % 96;
        float acc = attn_b[g];
        #pragma unroll 8
        for (int e = 0; e < 32; e++) {
            float vv = hcat[e * 8 + b] + hcat[768 + (64 + e) * 8 + b];
            acc = fmaf(vv, attn_w[g * 32 + e], acc);
        }
        int m = b0 + b;
        int head = (g & 31) >> 3;
        int d = g & 7;
        if (g < 32)      q_g[head * 8192 + m * 8 + d] = acc * 0.3535533905932738f;
        else if (g < 64) k_g[head * 8192 + m * 8 + d] = acc;
        else             v_g[head * 8192 + m * 8 + d] = acc;
    }
}

// =====================================================================
// Kernel 2: fused attention + MLP head. 128 CTAs x 256 thr, 8 rows each.
//   warp w = (head = w&3, rowgroup = w>>2): 4 query rows per warp,
//   k/v read directly from L2 (no smem staging), one pass of 1024 keys.
// =====================================================================
__global__ void __launch_bounds__(256, 1) attn_mlp_kernel(
    const float* __restrict__ ow, const float* __restrict__ ob,
    const float* __restrict__ d1w, const float* __restrict__ d1b,
    const float* __restrict__ bg1, const float* __restrict__ bb1,
    const float* __restrict__ d2w, const float* __restrict__ d2b,
    const float* __restrict__ bg2, const float* __restrict__ bb2,
    const float* __restrict__ d3w, const float* __restrict__ d3b,
    float* __restrict__ out)
{
    __shared__ float owT[1024], d1T[2048], d2T[2048], d3s[32];
    __shared__ float obs[32], d1bs[64], d2bs[32], s1v[64], sb1[64], s2v[32], sb2[32];
    __shared__ float att[8 * 32], z1[8 * 32], z2[8 * 64], z3[32 * 8];

    const int tid = threadIdx.x;
    const int lane = tid & 31, w = tid >> 5;
    const int r0 = blockIdx.x * 8;
    const float bnscale = rsqrtf(1.f + 1e-5f);

    // ---- stage MLP weights ----
    for (int i = tid; i < 1024; i += 256) { int o = i & 31, e = i >> 5; owT[e * 32 + o] = ow[o * 32 + e]; }
    for (int i = tid; i < 2048; i += 256) { int o = i & 63, e = i >> 6; d1T[e * 64 + o] = d1w[o * 32 + e]; }
    for (int i = tid; i < 2048; i += 256) { int o = i & 31, e = i >> 5; d2T[e * 32 + o] = d2w[o * 64 + e]; }
    if (tid < 32) { d3s[tid] = d3w[tid]; obs[tid] = ob[tid]; d2bs[tid] = d2b[tid]; s2v[tid] = bg2[tid] * bnscale; sb2[tid] = bb2[tid]; }
    if (tid < 64) { d1bs[tid] = d1b[tid]; s1v[tid] = bg1[tid] * bnscale; sb1[tid] = bb1[tid]; }

    // ---- attention: warp = (head, 4-row group), direct L2 k/v ----
    {
        const int head = w & 3;
        const int rg = w >> 2;          // 0 or 1
        const float* qbase = q_g + head * 8192 + (r0 + rg * 4) * 8;
        float4 qa[4], qb[4];
        #pragma unroll
        for (int r = 0; r < 4; r++) {
            const float4* qp = (const float4*)(qbase + r * 8);
            qa[r] = qp[0]; qb[r] = qp[1];
        }

        const float4* kg = (const float4*)(k_g + head * 8192);
        const float4* vg = (const float4*)(v_g + head * 8192);

        float sums[4] = {0.f, 0.f, 0.f, 0.f};
        float acc[4][8];
        #pragma unroll
        for (int r = 0; r < 4; r++)
            #pragma unroll
            for (int d = 0; d < 8; d++) acc[r][d] = 0.f;

        #pragma unroll 4
        for (int mi = 0; mi < 32; mi++) {
            int m = lane + mi * 32;
            float4 ka = kg[m * 2], kb = kg[m * 2 + 1];
            float4 va = vg[m * 2], vb = vg[m * 2 + 1];
            #pragma unroll
            for (int r = 0; r < 4; r++) {
                float s = qa[r].x * ka.x;
                s = fmaf(qa[r].y, ka.y, s);
                s = fmaf(qa[r].z, ka.z, s);
                s = fmaf(qa[r].w, ka.w, s);
                s = fmaf(qb[r].x, kb.x, s);
                s = fmaf(qb[r].y, kb.y, s);
                s = fmaf(qb[r].z, kb.z, s);
                s = fmaf(qb[r].w, kb.w, s);
                float e = __expf(s);
                sums[r] += e;
                acc[r][0] = fmaf(e, va.x, acc[r][0]);
                acc[r][1] = fmaf(e, va.y, acc[r][1]);
                acc[r][2] = fmaf(e, va.z, acc[r][2]);
                acc[r][3] = fmaf(e, va.w, acc[r][3]);
                acc[r][4] = fmaf(e, vb.x, acc[r][4]);
                acc[r][5] = fmaf(e, vb.y, acc[r][5]);
                acc[r][6] = fmaf(e, vb.z, acc[r][6]);
                acc[r][7] = fmaf(e, vb.w, acc[r][7]);
            }
        }
        // butterfly reduce across the warp
        #pragma unroll
        for (int o = 16; o > 0; o >>= 1) {
            #pragma unroll
            for (int r = 0; r < 4; r++) {
                sums[r] += __shfl_xor_sync(0xffffffffu, sums[r], o);
                #pragma unroll
                for (int d = 0; d < 8; d++)
                    acc[r][d] += __shfl_xor_sync(0xffffffffu, acc[r][d], o);
            }
        }
        if (lane < 4) {
            int row = rg * 4 + lane;
            float inv = 1.f / sums[lane];
            #pragma unroll
            for (int d = 0; d < 8; d++)
                att[row * 32 + head * 8 + d] = acc[lane][d] * inv;
        }
    }
    __syncthreads();

    // ---- attention output projection: 8x32 = 256 outputs ----
    {
        int b = tid >> 5, o = tid & 31;
        float a = obs[o];
        #pragma unroll 8
        for (int e = 0; e < 32; e++) a += att[b * 32 + e] * owT[e * 32 + o];
        z1[b * 32 + o] = a;
    }
    __syncthreads();

    // ---- dense1 + bn1 + relu: 8x64 = 512 outputs ----
    for (int i = tid; i < 512; i += 256) {
        int b = i >> 6, o = i & 63;
        float a = d1bs[o];
        #pragma unroll 8
        for (int e = 0; e < 32; e++) a += z1[b * 32 + e] * d1T[e * 64 + o];
        a = a * s1v[o] + sb1[o];
        z2[b * 64 + o] = fmaxf(a, 0.f);
    }
    __syncthreads();

    // ---- dense2 + bn2 + relu: 8x32 (store transposed [o][b]) ----
    {
        int b = tid >> 5, o = tid & 31;
        float a = d2bs[o];
        #pragma unroll 8
        for (int e = 0; e < 64; e++) a += z2[b * 64 + e] * d2T[e * 32 + o];
        a = a * s2v[o] + sb2[o];
        z3[o * 8 + b] = fmaxf(a, 0.f);
    }
    __syncthreads();

    // ---- dense3 + sigmoid ----
    if (tid < 8) {
        int b = tid;
        float a = d3b[0];
        #pragma unroll 8
        for (int e = 0; e < 32; e++) a += z3[e * 8 + b] * d3s[e];
        out[r0 + b] = 1.f / (1.f + __expf(-a));
    }
}

// =====================================================================
extern "C" void kernel_launch(void* const* d_in, const int* in_sizes, int n_in,
                              void* d_out, int out_size)
{
    const float* x      = (const float*)d_in[0];
    const float* emb_w  = (const float*)d_in[1];
    const float* emb_b  = (const float*)d_in[2];
    const float* l1_wih = (const float*)d_in[3];
    const float* l1_whh = (const float*)d_in[4];
    const float* l1_bih = (const float*)d_in[5];
    const float* l1_bhh = (const float*)d_in[6];
    const float* l2_wih = (const float*)d_in[7];
    const float* l2_whh = (const float*)d_in[8];
    const float* l2_bih = (const float*)d_in[9];
    const float* l2_bhh = (const float*)d_in[10];
    const float* attn_w = (const float*)d_in[11];
    const float* attn_b = (const float*)d_in[12];
    const float* attn_ow = (const float*)d_in[13];
    const float* attn_ob = (const float*)d_in[14];
    const float* d1_w   = (const float*)d_in[15];
    const float* d1_b   = (const float*)d_in[16];
    const float* bn1_g  = (const float*)d_in[17];
    const float* bn1_b  = (const float*)d_in[18];
    const float* d2_w   = (const float*)d_in[19];
    const float* d2_b   = (const float*)d_in[20];
    const float* bn2_g  = (const float*)d_in[21];
    const float* bn2_b  = (const float*)d_in[22];
    const float* d3_w   = (const float*)d_in[23];
    const float* d3_b   = (const float*)d_in[24];
    float* out = (float*)d_out;

    const int smem1 = 20672 * 4;   // 82,688 B
    cudaFuncSetAttribute(lstm_kernel, cudaFuncAttributeMaxDynamicSharedMemorySize, smem1);

    lstm_kernel<<<128, 896, smem1>>>(x, emb_w, emb_b,
                                     l1_wih, l1_whh, l1_bih, l1_bhh,
                                     l2_wih, l2_whh, l2_bih, l2_bhh,
                                     attn_w, attn_b);
    attn_mlp_kernel<<<128, 256>>>(attn_ow, attn_ob, d1_w, d1_b,
                                  bn1_g, bn1_b, d2_w, d2_b,
                                  bn2_g, bn2_b, d3_w, d3_b, out);
}